// round 8
// baseline (speedup 1.0000x reference)
#include <cuda_runtime.h>
#include <cuda_bf16.h>
#include <math.h>
#include <stdint.h>

#define NEG_SLOPE 0.2f
#define EPS_BN 1e-5f
#define N_NODES 20000
#define F_IN_D 128
#define E_EDGES 320000
#define E_TOT (E_EDGES + N_NODES)
#define HD_MAX 256
#define G_GRAPHS 64
#define OUT_DIM 128
#define NCLS_D 10
#define NSTAT_BLK 160

// ---------------- scratch ----------------
__device__ float g_h[N_NODES * HD_MAX];
__device__ float g_o[N_NODES * HD_MAX];
__device__ __nv_bfloat16 g_ahi[N_NODES * HD_MAX];
__device__ __nv_bfloat16 g_alo[N_NODES * HD_MAX];
__device__ __nv_bfloat16 g_wthi[131072];
__device__ __nv_bfloat16 g_wtlo[131072];
__device__ float g_es[N_NODES * 4];
__device__ float g_ed[N_NODES * 4];
__device__ int   g_deg[N_NODES];
__device__ int   g_rowptr[N_NODES + 1];
__device__ int   g_cursor[N_NODES];
__device__ int   g_csrc[E_TOT];
__device__ float g_bnpart[NSTAT_BLK * 2 * HD_MAX];
__device__ float g_scale[HD_MAX];
__device__ float g_shift[HD_MAX];
__device__ float g_feat[G_GRAPHS * OUT_DIM];
__device__ int   g_start[G_GRAPHS + 1];

// ---------------- utility ----------------
__global__ void k_zero_i(int* p, int n) {
    int i = blockIdx.x * blockDim.x + threadIdx.x;
    if (i < n) p[i] = 0;
}

// ---------------- CSR build ----------------
__global__ void k_deg(const int* __restrict__ ei, int E, int ET, int* __restrict__ deg) {
    int e = blockIdx.x * blockDim.x + threadIdx.x;
    if (e >= ET) return;
    int d = (e < E) ? ei[E + e] : (e - E);
    atomicAdd(&deg[d], 1);
}

__global__ void k_scan(const int* __restrict__ deg, int* __restrict__ rowptr,
                       int* __restrict__ cursor, int n) {
    __shared__ int sh[1024];
    int t = threadIdx.x;
    int items = (n + 1023) / 1024;
    int b0 = t * items;
    int loc = 0;
    for (int i = 0; i < items; i++) {
        int idx = b0 + i;
        if (idx < n) loc += deg[idx];
    }
    sh[t] = loc;
    __syncthreads();
    for (int off = 1; off < 1024; off <<= 1) {
        int v = (t >= off) ? sh[t - off] : 0;
        __syncthreads();
        sh[t] += v;
        __syncthreads();
    }
    int run = sh[t] - loc;
    for (int i = 0; i < items; i++) {
        int idx = b0 + i;
        if (idx < n) {
            rowptr[idx] = run;
            cursor[idx] = run;
            run += deg[idx];
        }
    }
    if (t == 1023) rowptr[n] = sh[1023];
}

__global__ void k_fill(const int* __restrict__ ei, int E, int ET,
                       int* __restrict__ cursor, int* __restrict__ csrc) {
    int e = blockIdx.x * blockDim.x + threadIdx.x;
    if (e >= ET) return;
    int s, d;
    if (e < E) { s = ei[e]; d = ei[E + e]; }
    else { s = e - E; d = e - E; }
    int pos = atomicAdd(&cursor[d], 1);
    csrc[pos] = s;
}

// graph ranges (batch sorted); also zero feat
__global__ void k_ranges(const int* __restrict__ batch, int n, int* __restrict__ start,
                         float* __restrict__ feat) {
    int g = threadIdx.x;
    for (int i = g; i < G_GRAPHS * OUT_DIM; i += 128) feat[i] = 0.f;
    if (g > G_GRAPHS) return;
    if (g == G_GRAPHS) { start[G_GRAPHS] = n; return; }
    int lo = 0, hi = n;
    while (lo < hi) {
        int mid = (lo + hi) >> 1;
        if (batch[mid] < g) lo = mid + 1; else hi = mid;
    }
    start[g] = lo;
}

// ---------------- bf16 split helpers ----------------
__device__ __forceinline__ uint32_t pack_hi(float x0, float x1) {
    __nv_bfloat16 h0 = __float2bfloat16_rn(x0);
    __nv_bfloat16 h1 = __float2bfloat16_rn(x1);
    return (uint32_t)__bfloat16_as_ushort(h0) | ((uint32_t)__bfloat16_as_ushort(h1) << 16);
}
__device__ __forceinline__ uint32_t pack_lo(float x0, float x1) {
    __nv_bfloat16 h0 = __float2bfloat16_rn(x0);
    __nv_bfloat16 h1 = __float2bfloat16_rn(x1);
    __nv_bfloat16 l0 = __float2bfloat16_rn(x0 - __bfloat162float(h0));
    __nv_bfloat16 l1 = __float2bfloat16_rn(x1 - __bfloat162float(h1));
    return (uint32_t)__bfloat16_as_ushort(l0) | ((uint32_t)__bfloat16_as_ushort(l1) << 16);
}
__device__ __forceinline__ void mma_bf16(float* c, const uint32_t* a, uint32_t b0, uint32_t b1) {
    asm volatile(
        "mma.sync.aligned.m16n8k16.row.col.f32.bf16.bf16.f32 "
        "{%0,%1,%2,%3}, {%4,%5,%6,%7}, {%8,%9}, {%0,%1,%2,%3};"
        : "+f"(c[0]), "+f"(c[1]), "+f"(c[2]), "+f"(c[3])
        : "r"(a[0]), "r"(a[1]), "r"(a[2]), "r"(a[3]), "r"(b0), "r"(b1));
}
__device__ __forceinline__ void cp16(uint32_t dst, const void* src, bool valid) {
    int sz = valid ? 16 : 0;
    asm volatile("cp.async.cg.shared.global [%0], [%1], 16, %2;\n"
                 :: "r"(dst), "l"(src), "r"(sz));
}
#define CP_COMMIT() asm volatile("cp.async.commit_group;\n" ::: "memory")
#define CP_WAIT2()  asm volatile("cp.async.wait_group 2;\n" ::: "memory")

// ---------------- fp32 -> bf16 hi/lo convert (optional fused BN+ReLU) ----------------
template <bool FUSE>
__global__ void k_cvt(const float* __restrict__ in, __nv_bfloat16* __restrict__ hi,
                      __nv_bfloat16* __restrict__ lo, const float* __restrict__ sc,
                      const float* __restrict__ sh, int total, int C) {
    int i = blockIdx.x * blockDim.x + threadIdx.x;
    if (i * 4 >= total) return;
    float4 v = ((const float4*)in)[i];
    if (FUSE) {
        int c = (i * 4) % C;
        v.x = fmaxf(v.x * sc[c] + sh[c], 0.f);
        v.y = fmaxf(v.y * sc[c + 1] + sh[c + 1], 0.f);
        v.z = fmaxf(v.z * sc[c + 2] + sh[c + 2], 0.f);
        v.w = fmaxf(v.w * sc[c + 3] + sh[c + 3], 0.f);
    }
    ((uint2*)hi)[i] = make_uint2(pack_hi(v.x, v.y), pack_hi(v.z, v.w));
    ((uint2*)lo)[i] = make_uint2(pack_lo(v.x, v.y), pack_lo(v.z, v.w));
}

// ---------------- convert+transpose all three W: W[K][Nd] -> WT[Nd][K] bf16 hi/lo ----
__global__ void k_cvt_w3(const float* __restrict__ W0, const float* __restrict__ W1,
                         const float* __restrict__ W2, __nv_bfloat16* __restrict__ hi,
                         __nv_bfloat16* __restrict__ lo) {
    int i = blockIdx.x * blockDim.x + threadIdx.x;
    if (i >= 131072) return;
    const float* W; int K, Nd, off, j = i;
    if (j < 32768)       { W = W0; K = 128; Nd = 256; off = 0; }
    else if (j < 98304)  { W = W1; K = 256; Nd = 256; off = 32768; j -= 32768; }
    else                 { W = W2; K = 256; Nd = 128; off = 98304; j -= 98304; }
    int n = j / K, k = j % K;
    float v = W[k * Nd + n];
    __nv_bfloat16 h = __float2bfloat16_rn(v);
    hi[off + j] = h;
    lo[off + j] = __float2bfloat16_rn(v - __bfloat162float(h));
}

// ---------------- GEMM: bf16 hi/lo operands, cp.async 3-stage pipeline --------------
// A: [M][K] bf16 (hi,lo); B: [Nd][K] bf16 (hi,lo) (i.e. W^T). C[M][Nd] fp32.
// smem stage: A_hi(128x16), A_lo, B_hi(128x16), B_lo; rows padded to 48B (12 words).
#define KT 16
#define STG_W 6144          // words per stage (24576 B)
#define OFF_AL 1536
#define OFF_BH 3072
#define OFF_BL 4608
__global__ __launch_bounds__(256, 2) void k_gemm_bf16(
        const __nv_bfloat16* __restrict__ Ahi, const __nv_bfloat16* __restrict__ Alo,
        const __nv_bfloat16* __restrict__ Bhi, const __nv_bfloat16* __restrict__ Blo,
        float* __restrict__ C, int M, int K, int Nd) {
    extern __shared__ uint32_t smw[];
    int t = threadIdx.x;
    int bm = blockIdx.x * 128, bn = blockIdx.y * 128;
    int warp = t >> 5, lane = t & 31;
    int wm = (warp >> 2) * 64, wn = (warp & 3) * 32;
    int gid = lane >> 2, tig = lane & 3;

    // staging: thread handles row r (for both A and B tiles), 16B chunk cch
    int r = t >> 1, cch = t & 1;
    bool av = (bm + r) < M;
    const __nv_bfloat16* agh = Ahi + (size_t)(bm + r) * K + cch * 8;
    const __nv_bfloat16* agl = Alo + (size_t)(bm + r) * K + cch * 8;
    const __nv_bfloat16* bgh = Bhi + (size_t)(bn + r) * K + cch * 8;
    const __nv_bfloat16* bgl = Blo + (size_t)(bn + r) * K + cch * 8;
    uint32_t dRow = (uint32_t)__cvta_generic_to_shared(smw) + r * 48 + cch * 16;

    auto issue = [&](int s, int k0, bool pred) {
        if (pred) {
            uint32_t o = (uint32_t)s * (STG_W * 4);
            cp16(dRow + o,                 agh + k0, av);
            cp16(dRow + o + OFF_AL * 4,    agl + k0, av);
            cp16(dRow + o + OFF_BH * 4,    bgh + k0, true);
            cp16(dRow + o + OFF_BL * 4,    bgl + k0, true);
        }
        CP_COMMIT();
    };

    float acc[4][4][4];
#pragma unroll
    for (int mt = 0; mt < 4; mt++)
#pragma unroll
        for (int nt = 0; nt < 4; nt++)
#pragma unroll
            for (int c = 0; c < 4; c++) acc[mt][nt][c] = 0.f;

    int nk = K / KT;
    issue(0, 0, true);
    issue(1, KT, 1 < nk);
    issue(2, 2 * KT, 2 < nk);

    for (int kt = 0; kt < nk; kt++) {
        CP_WAIT2();
        __syncthreads();
        int sb = (kt % 3) * STG_W;

        uint32_t fbh[4][2], fbl[4][2];
#pragma unroll
        for (int nt = 0; nt < 4; nt++) {
            int c0 = (wn + nt * 8 + gid) * 12;
            fbh[nt][0] = smw[sb + OFF_BH + c0 + tig];
            fbh[nt][1] = smw[sb + OFF_BH + c0 + tig + 4];
            fbl[nt][0] = smw[sb + OFF_BL + c0 + tig];
            fbl[nt][1] = smw[sb + OFF_BL + c0 + tig + 4];
        }
#pragma unroll
        for (int mt = 0; mt < 4; mt++) {
            int r0 = (wm + mt * 16 + gid) * 12;
            int r8 = r0 + 96;  // +8 rows
            uint32_t ah[4], al[4];
            ah[0] = smw[sb + r0 + tig];
            ah[1] = smw[sb + r8 + tig];
            ah[2] = smw[sb + r0 + tig + 4];
            ah[3] = smw[sb + r8 + tig + 4];
            al[0] = smw[sb + OFF_AL + r0 + tig];
            al[1] = smw[sb + OFF_AL + r8 + tig];
            al[2] = smw[sb + OFF_AL + r0 + tig + 4];
            al[3] = smw[sb + OFF_AL + r8 + tig + 4];
#pragma unroll
            for (int nt = 0; nt < 4; nt++)
                mma_bf16(acc[mt][nt], ah, fbh[nt][0], fbh[nt][1]);
#pragma unroll
            for (int nt = 0; nt < 4; nt++)
                mma_bf16(acc[mt][nt], ah, fbl[nt][0], fbl[nt][1]);
#pragma unroll
            for (int nt = 0; nt < 4; nt++)
                mma_bf16(acc[mt][nt], al, fbh[nt][0], fbh[nt][1]);
        }
        __syncthreads();
        int ks = kt + 3;
        issue(kt % 3, ks * KT, ks < nk);
    }

#pragma unroll
    for (int mt = 0; mt < 4; mt++) {
        int r0i = bm + wm + mt * 16 + gid;
        int r1i = r0i + 8;
#pragma unroll
        for (int nt = 0; nt < 4; nt++) {
            int cc = bn + wn + nt * 8 + tig * 2;
            if (r0i < M) *(float2*)&C[(size_t)r0i * Nd + cc] =
                make_float2(acc[mt][nt][0], acc[mt][nt][1]);
            if (r1i < M) *(float2*)&C[(size_t)r1i * Nd + cc] =
                make_float2(acc[mt][nt][2], acc[mt][nt][3]);
        }
    }
}

// ---------------- per-node attention src/dst scores ----------------
template <int H, int D>
__global__ void k_srcdst(const float* __restrict__ h, const float* __restrict__ asrc,
                         const float* __restrict__ adst, float* __restrict__ es,
                         float* __restrict__ ed, int n) {
    constexpr int HD = H * D, PL = HD / 32;
    int w = (blockIdx.x * blockDim.x + threadIdx.x) >> 5;
    int lane = threadIdx.x & 31;
    if (w >= n) return;
    float ps[H], pd[H];
#pragma unroll
    for (int hh = 0; hh < H; hh++) { ps[hh] = 0.f; pd[hh] = 0.f; }
#pragma unroll
    for (int k = 0; k < PL; k++) {
        int c = lane + 32 * k;
        float hv = h[(size_t)w * HD + c];
        const int hh = (32 * k) / D;
        ps[hh] += hv * asrc[c];
        pd[hh] += hv * adst[c];
    }
#pragma unroll
    for (int off = 16; off; off >>= 1) {
#pragma unroll
        for (int hh = 0; hh < H; hh++) {
            ps[hh] += __shfl_xor_sync(0xffffffffu, ps[hh], off);
            pd[hh] += __shfl_xor_sync(0xffffffffu, pd[hh], off);
        }
    }
    if (lane == 0) {
#pragma unroll
        for (int hh = 0; hh < H; hh++) {
            es[w * H + hh] = ps[hh];
            ed[w * H + hh] = pd[hh];
        }
    }
}

// ---------------- single-pass softmax + aggregation ----------------
template <int H, int D>
__global__ __launch_bounds__(256) void k_agg_fused(
        const float* __restrict__ h, const float* __restrict__ es,
        const float* __restrict__ ed, const int* __restrict__ rowptr,
        const int* __restrict__ csrc, const float* __restrict__ bias,
        float* __restrict__ outp, int n) {
    constexpr int HD = H * D, PL = HD / 32, NV = PL / 4;
    int node = (blockIdx.x * blockDim.x + threadIdx.x) >> 5;
    int lane = threadIdx.x & 31;
    if (node >= n) return;
    const int hme = (lane * PL) / D;

    float edme = ed[node * H + hme];
    int p0 = rowptr[node], p1 = rowptr[node + 1];
    float4 acc[NV];
#pragma unroll
    for (int q = 0; q < NV; q++) acc[q] = make_float4(0.f, 0.f, 0.f, 0.f);
    float z = 0.f;
#pragma unroll 2
    for (int p = p0; p < p1; p++) {
        int s = csrc[p];
        float e = es[s * H + hme] + edme;
        e = (e > 0.f) ? e : NEG_SLOPE * e;
        float w = __expf(e);
        z += w;
        const float4* hs = (const float4*)(h + (size_t)s * HD + lane * PL);
#pragma unroll
        for (int q = 0; q < NV; q++) {
            float4 v = hs[q];
            acc[q].x += v.x * w; acc[q].y += v.y * w;
            acc[q].z += v.z * w; acc[q].w += v.w * w;
        }
    }
    float iz = 1.f / z;
    const float4* bb = (const float4*)(bias + lane * PL);
    float4* op = (float4*)(outp + (size_t)node * HD + lane * PL);
#pragma unroll
    for (int q = 0; q < NV; q++) {
        float4 b = bb[q];
        op[q] = make_float4(acc[q].x * iz + b.x, acc[q].y * iz + b.y,
                            acc[q].z * iz + b.z, acc[q].w * iz + b.w);
    }
}

// ---------------- BN stats ----------------
__global__ void k_bnstats(const float* __restrict__ x, int n, int C,
                          float* __restrict__ part) {
    int c = threadIdx.x;
    int chunk = (n + gridDim.x - 1) / gridDim.x;
    int r0 = blockIdx.x * chunk;
    int r1 = min(n, r0 + chunk);
    float s = 0.f, q = 0.f;
    int r = r0;
    for (; r + 3 < r1; r += 4) {
        float v0 = x[(size_t)r * C + c];
        float v1 = x[(size_t)(r + 1) * C + c];
        float v2 = x[(size_t)(r + 2) * C + c];
        float v3 = x[(size_t)(r + 3) * C + c];
        s += v0 + v1 + v2 + v3;
        q += v0 * v0 + v1 * v1 + v2 * v2 + v3 * v3;
    }
    for (; r < r1; r++) {
        float v = x[(size_t)r * C + c];
        s += v; q += v * v;
    }
    part[(size_t)blockIdx.x * 2 * C + c] = s;
    part[(size_t)blockIdx.x * 2 * C + C + c] = q;
}

__global__ void k_bnfinal(const float* __restrict__ gamma, const float* __restrict__ beta,
                          int n, int C, const float* __restrict__ part,
                          float* __restrict__ scale, float* __restrict__ shift) {
    int c = threadIdx.x;
    if (c >= C) return;
    float s = 0.f, q = 0.f;
    for (int b = 0; b < NSTAT_BLK; b++) {
        s += part[(size_t)b * 2 * C + c];
        q += part[(size_t)b * 2 * C + C + c];
    }
    float mu = s / (float)n;
    float var = q / (float)n - mu * mu;
    float sc = gamma[c] * rsqrtf(var + EPS_BN);
    scale[c] = sc;
    shift[c] = beta[c] - mu * sc;
}

// ---------------- pooling (fused BN+ReLU of last layer) ----------------
__global__ void k_pool(const float* __restrict__ o, const int* __restrict__ start,
                       const float* __restrict__ scale, const float* __restrict__ shift,
                       float* __restrict__ feat) {
    __shared__ float sm[4][OUT_DIM];
    int g = blockIdx.x;
    int part = blockIdx.y;
    int c = threadIdx.x & 127;
    int rgrp = threadIdx.x >> 7;
    int s0 = start[g], s1 = start[g + 1];
    int len = s1 - s0;
    int chunk = (len + 3) >> 2;
    int r0 = s0 + part * chunk;
    int r1 = min(s1, r0 + chunk);
    float sc = scale[c], sh = shift[c];
    float sum = 0.f;
    for (int r = r0 + rgrp; r < r1; r += 4) {
        float v = o[(size_t)r * OUT_DIM + c];
        sum += fmaxf(v * sc + sh, 0.f);
    }
    sm[rgrp][c] = sum;
    __syncthreads();
    if (threadIdx.x < OUT_DIM) {
        float s = sm[0][c] + sm[1][c] + sm[2][c] + sm[3][c];
        atomicAdd(&feat[g * OUT_DIM + c], s);
    }
}

// ---------------- heads ----------------
__global__ void k_heads(const float* __restrict__ featsum, const int* __restrict__ start,
                        const float* __restrict__ clfW, const float* __restrict__ clfb,
                        const float* __restrict__ dW1, const float* __restrict__ db1,
                        const float* __restrict__ dW2, const float* __restrict__ db2,
                        float* __restrict__ out) {
    __shared__ float f[OUT_DIM];
    __shared__ float dh[64];
    int g = blockIdx.x, t = threadIdx.x;
    float c = (float)max(start[g + 1] - start[g], 1);
    f[t] = featsum[g * OUT_DIM + t] / c;
    out[G_GRAPHS * NCLS_D + G_GRAPHS * 2 + g * OUT_DIM + t] = f[t];
    __syncthreads();
    if (t < 64) {
        float s = db1[t];
        for (int k = 0; k < OUT_DIM; k++) s += f[k] * dW1[k * 64 + t];
        dh[t] = fmaxf(s, 0.f);
    }
    if (t < NCLS_D) {
        float s = clfb[t];
        for (int k = 0; k < OUT_DIM; k++) s += f[k] * clfW[k * NCLS_D + t];
        out[g * NCLS_D + t] = s;
    }
    __syncthreads();
    if (t < 2) {
        float s = db2[t];
        for (int k = 0; k < 64; k++) s += dh[k] * dW2[k * 2 + t];
        out[G_GRAPHS * NCLS_D + g * 2 + t] = s;
    }
}

// ---------------- launch ----------------
static inline int cdiv(int a, int b) { return (a + b - 1) / b; }

extern "C" void kernel_launch(void* const* d_in, const int* in_sizes, int n_in,
                              void* d_out, int out_size) {
    const float* x = (const float*)d_in[0];
    const int* ei = (const int*)d_in[1];
    const int* batch = (const int*)d_in[2];
    const float* W[3]   = {(const float*)d_in[3],  (const float*)d_in[9],  (const float*)d_in[15]};
    const float* Asr[3] = {(const float*)d_in[4],  (const float*)d_in[10], (const float*)d_in[16]};
    const float* Ads[3] = {(const float*)d_in[5],  (const float*)d_in[11], (const float*)d_in[17]};
    const float* Bi[3]  = {(const float*)d_in[6],  (const float*)d_in[12], (const float*)d_in[18]};
    const float* Ga[3]  = {(const float*)d_in[7],  (const float*)d_in[13], (const float*)d_in[19]};
    const float* Be[3]  = {(const float*)d_in[8],  (const float*)d_in[14], (const float*)d_in[20]};
    const float* clfW = (const float*)d_in[21];
    const float* clfb = (const float*)d_in[22];
    const float* dW1 = (const float*)d_in[23];
    const float* db1 = (const float*)d_in[24];
    const float* dW2 = (const float*)d_in[25];
    const float* db2 = (const float*)d_in[26];

    int N = in_sizes[0] / F_IN_D;
    int E = in_sizes[1] / 2;
    int ET = E + N;

    float *p_h, *p_o, *p_es, *p_ed, *p_part, *p_scale, *p_shift, *p_feat;
    __nv_bfloat16 *p_ahi, *p_alo, *p_wthi, *p_wtlo;
    int *p_deg, *p_rowptr, *p_cursor, *p_csrc, *p_start;
    cudaGetSymbolAddress((void**)&p_h, g_h);
    cudaGetSymbolAddress((void**)&p_o, g_o);
    cudaGetSymbolAddress((void**)&p_ahi, g_ahi);
    cudaGetSymbolAddress((void**)&p_alo, g_alo);
    cudaGetSymbolAddress((void**)&p_wthi, g_wthi);
    cudaGetSymbolAddress((void**)&p_wtlo, g_wtlo);
    cudaGetSymbolAddress((void**)&p_es, g_es);
    cudaGetSymbolAddress((void**)&p_ed, g_ed);
    cudaGetSymbolAddress((void**)&p_deg, g_deg);
    cudaGetSymbolAddress((void**)&p_rowptr, g_rowptr);
    cudaGetSymbolAddress((void**)&p_cursor, g_cursor);
    cudaGetSymbolAddress((void**)&p_csrc, g_csrc);
    cudaGetSymbolAddress((void**)&p_part, g_bnpart);
    cudaGetSymbolAddress((void**)&p_scale, g_scale);
    cudaGetSymbolAddress((void**)&p_shift, g_shift);
    cudaGetSymbolAddress((void**)&p_feat, g_feat);
    cudaGetSymbolAddress((void**)&p_start, g_start);

    cudaFuncSetAttribute(k_gemm_bf16, cudaFuncAttributeMaxDynamicSharedMemorySize,
                         3 * STG_W * 4);

    const int woff[3] = {0, 32768, 98304};
    const int Kd[3] = {F_IN_D, 256, 256};
    const int Hh[3] = {4, 4, 1};

    // order: cvt_w3, cvt_x, zero_i, gemm0 (launch idx 3 for the ncu window), CSR rest
    k_cvt_w3<<<cdiv(131072, 256), 256>>>(W[0], W[1], W[2], p_wthi, p_wtlo);
    k_cvt<false><<<cdiv(N * F_IN_D / 4, 256), 256>>>(x, p_ahi, p_alo, nullptr, nullptr,
                                                     N * F_IN_D, F_IN_D);
    k_zero_i<<<cdiv(N, 256), 256>>>(p_deg, N);
    {
        dim3 gg(cdiv(N, 128), 2);
        k_gemm_bf16<<<gg, 256, 3 * STG_W * 4>>>(p_ahi, p_alo, p_wthi, p_wtlo, p_h,
                                                N, Kd[0], 256);
    }
    k_deg<<<cdiv(ET, 256), 256>>>(ei, E, ET, p_deg);
    k_scan<<<1, 1024>>>(p_deg, p_rowptr, p_cursor, N);
    k_fill<<<cdiv(ET, 256), 256>>>(ei, E, ET, p_cursor, p_csrc);
    k_ranges<<<1, 128>>>(batch, N, p_start, p_feat);

    for (int li = 0; li < 3; li++) {
        int HD = (li < 2) ? 256 : 128;
        if (li > 0) {
            // BN(prev) + ReLU + bf16 split
            k_cvt<true><<<cdiv(N * Kd[li] / 4, 256), 256>>>(p_o, p_ahi, p_alo, p_scale,
                                                            p_shift, N * Kd[li], Kd[li]);
            dim3 gg(cdiv(N, 128), HD / 128);
            k_gemm_bf16<<<gg, 256, 3 * STG_W * 4>>>(p_ahi, p_alo, p_wthi + woff[li],
                                                    p_wtlo + woff[li], p_h, N, Kd[li], HD);
        }

        int aggBlocks = cdiv(N * 32, 256);
        if (Hh[li] == 4) {
            k_srcdst<4, 64><<<aggBlocks, 256>>>(p_h, Asr[li], Ads[li], p_es, p_ed, N);
            k_agg_fused<4, 64><<<aggBlocks, 256>>>(p_h, p_es, p_ed, p_rowptr, p_csrc,
                                                   Bi[li], p_o, N);
        } else {
            k_srcdst<1, 128><<<aggBlocks, 256>>>(p_h, Asr[li], Ads[li], p_es, p_ed, N);
            k_agg_fused<1, 128><<<aggBlocks, 256>>>(p_h, p_es, p_ed, p_rowptr, p_csrc,
                                                    Bi[li], p_o, N);
        }

        k_bnstats<<<NSTAT_BLK, HD>>>(p_o, N, HD, p_part);
        k_bnfinal<<<1, HD>>>(Ga[li], Be[li], N, HD, p_part, p_scale, p_shift);
    }

    // --- pooling + heads ---
    {
        dim3 pg(G_GRAPHS, 4);
        k_pool<<<pg, 512>>>(p_o, p_start, p_scale, p_shift, p_feat);
    }
    k_heads<<<G_GRAPHS, 128>>>(p_feat, p_start, clfW, clfb, dW1, db1, dW2, db2,
                               (float*)d_out);
}

// round 9
// speedup vs baseline: 1.1902x; 1.1902x over previous
#include <cuda_runtime.h>
#include <cuda_bf16.h>
#include <math.h>
#include <stdint.h>

#define NEG_SLOPE 0.2f
#define EPS_BN 1e-5f
#define N_NODES 20000
#define F_IN_D 128
#define E_EDGES 320000
#define E_TOT (E_EDGES + N_NODES)
#define HD_MAX 256
#define G_GRAPHS 64
#define OUT_DIM 128
#define NCLS_D 10

// ---------------- scratch ----------------
__device__ float g_h[N_NODES * HD_MAX];
__device__ float g_o[N_NODES * HD_MAX];
__device__ float g_es[N_NODES * 4];
__device__ float g_ed[N_NODES * 4];
__device__ int   g_deg[N_NODES];
__device__ int   g_rowptr[N_NODES + 1];
__device__ int   g_cursor[N_NODES];
__device__ int   g_csrc[E_TOT];
__device__ float g_bnstat[3 * 2 * HD_MAX];
__device__ float g_scale[HD_MAX];
__device__ float g_shift[HD_MAX];
__device__ float g_feat[G_GRAPHS * OUT_DIM];
__device__ int   g_start[G_GRAPHS + 1];

// ---------------- utility ----------------
__global__ void k_zero_i(int* p, int n) {
    int i = blockIdx.x * blockDim.x + threadIdx.x;
    if (i < n) p[i] = 0;
}

// ---------------- CSR build ----------------
__global__ void k_deg(const int* __restrict__ ei, int E, int ET, int* __restrict__ deg) {
    int e = blockIdx.x * blockDim.x + threadIdx.x;
    if (e >= ET) return;
    int d = (e < E) ? ei[E + e] : (e - E);
    atomicAdd(&deg[d], 1);
}

__global__ void k_scan(const int* __restrict__ deg, int* __restrict__ rowptr,
                       int* __restrict__ cursor, int n) {
    __shared__ int sh[1024];
    int t = threadIdx.x;
    int items = (n + 1023) / 1024;
    int b0 = t * items;
    int loc = 0;
    for (int i = 0; i < items; i++) {
        int idx = b0 + i;
        if (idx < n) loc += deg[idx];
    }
    sh[t] = loc;
    __syncthreads();
    for (int off = 1; off < 1024; off <<= 1) {
        int v = (t >= off) ? sh[t - off] : 0;
        __syncthreads();
        sh[t] += v;
        __syncthreads();
    }
    int run = sh[t] - loc;
    for (int i = 0; i < items; i++) {
        int idx = b0 + i;
        if (idx < n) {
            rowptr[idx] = run;
            cursor[idx] = run;
            run += deg[idx];
        }
    }
    if (t == 1023) rowptr[n] = sh[1023];
}

__global__ void k_fill(const int* __restrict__ ei, int E, int ET,
                       int* __restrict__ cursor, int* __restrict__ csrc) {
    int e = blockIdx.x * blockDim.x + threadIdx.x;
    if (e >= ET) return;
    int s, d;
    if (e < E) { s = ei[e]; d = ei[E + e]; }
    else { s = e - E; d = e - E; }
    int pos = atomicAdd(&cursor[d], 1);
    csrc[pos] = s;
}

// graph ranges (batch sorted); also zero feat + bn stat accumulators
__global__ void k_ranges(const int* __restrict__ batch, int n, int* __restrict__ start,
                         float* __restrict__ feat, float* __restrict__ stat) {
    int g = threadIdx.x;
    for (int i = g; i < G_GRAPHS * OUT_DIM; i += 128) feat[i] = 0.f;
    for (int i = g; i < 3 * 2 * HD_MAX; i += 128) stat[i] = 0.f;
    if (g > G_GRAPHS) return;
    if (g == G_GRAPHS) { start[G_GRAPHS] = n; return; }
    int lo = 0, hi = n;
    while (lo < hi) {
        int mid = (lo + hi) >> 1;
        if (batch[mid] < g) lo = mid + 1; else hi = mid;
    }
    start[g] = lo;
}

// ---------------- bf16 split helpers ----------------
__device__ __forceinline__ uint32_t pack_hi(float x0, float x1) {
    __nv_bfloat16 h0 = __float2bfloat16_rn(x0);
    __nv_bfloat16 h1 = __float2bfloat16_rn(x1);
    return (uint32_t)__bfloat16_as_ushort(h0) | ((uint32_t)__bfloat16_as_ushort(h1) << 16);
}
__device__ __forceinline__ uint32_t pack_lo(float x0, float x1) {
    __nv_bfloat16 h0 = __float2bfloat16_rn(x0);
    __nv_bfloat16 h1 = __float2bfloat16_rn(x1);
    __nv_bfloat16 l0 = __float2bfloat16_rn(x0 - __bfloat162float(h0));
    __nv_bfloat16 l1 = __float2bfloat16_rn(x1 - __bfloat162float(h1));
    return (uint32_t)__bfloat16_as_ushort(l0) | ((uint32_t)__bfloat16_as_ushort(l1) << 16);
}
__device__ __forceinline__ void mma_bf16(float* c, const uint32_t* a, uint32_t b0, uint32_t b1) {
    asm volatile(
        "mma.sync.aligned.m16n8k16.row.col.f32.bf16.bf16.f32 "
        "{%0,%1,%2,%3}, {%4,%5,%6,%7}, {%8,%9}, {%0,%1,%2,%3};"
        : "+f"(c[0]), "+f"(c[1]), "+f"(c[2]), "+f"(c[3])
        : "r"(a[0]), "r"(a[1]), "r"(a[2]), "r"(a[3]), "r"(b0), "r"(b1));
}

// ---------------- Tensor-core GEMM: bf16 2-term split + fused attention scores ------
// Epilogue computes es[row,head] = sum_c h[row,c]*asrc[c], ed likewise (c within head).
// Column-block CTAs own disjoint heads -> plain global stores, no atomics.
#define SMP2 136
template <bool FUSE>
__global__ __launch_bounds__(256, 2) void k_gemm_tc(const float* __restrict__ A,
                                                    const float* __restrict__ B,
                                                    float* __restrict__ C,
                                                    int M, int K, int Nd, int D,
                                                    const float* __restrict__ scale,
                                                    const float* __restrict__ shift,
                                                    const float* __restrict__ asrc,
                                                    const float* __restrict__ adst,
                                                    float* __restrict__ es,
                                                    float* __restrict__ ed) {
    __shared__ __align__(16) uint32_t Ah[2][8][SMP2];
    __shared__ __align__(16) uint32_t Al[2][8][SMP2];
    __shared__ __align__(16) uint32_t Bh[2][8][SMP2];
    __shared__ __align__(16) uint32_t Bl[2][8][SMP2];
    __shared__ float ssc[HD_MAX], ssh[HD_MAX];
    __shared__ float sAs[128], sAd[128];
    __shared__ float sE[128][2][2];
    int t = threadIdx.x;
    int bm = blockIdx.x * 128, bn = blockIdx.y * 128;

    if (t < 128) { sAs[t] = asrc[bn + t]; sAd[t] = adst[bn + t]; }
    for (int i = t; i < 512; i += 256) ((float*)sE)[i] = 0.f;
    if (FUSE) {
        for (int i = t; i < K; i += 256) { ssc[i] = scale[i]; ssh[i] = shift[i]; }
    }
    __syncthreads();

    int warp = t >> 5, lane = t & 31;
    int wm = (warp >> 2) * 64, wn = (warp & 3) * 32;
    int gid = lane >> 2, tig = lane & 3;

    int ar = t >> 1, akb = (t & 1) * 8;
    bool avalid = (bm + ar) < M;
    const float* Ap = A + (size_t)(bm + ar) * K + akb;
    int bkr = warp * 2, bcc = lane * 4;
    const float* Bp = B + (size_t)bkr * Nd + bn + bcc;

    float acc[4][4][4];
#pragma unroll
    for (int mt = 0; mt < 4; mt++)
#pragma unroll
        for (int nt = 0; nt < 4; nt++)
#pragma unroll
            for (int c = 0; c < 4; c++) acc[mt][nt][c] = 0.f;

    float4 a0, a1, b0, b1;

    auto stage = [&](int buf, int k0) {
        float v[8] = {a0.x, a0.y, a0.z, a0.w, a1.x, a1.y, a1.z, a1.w};
        if (FUSE) {
#pragma unroll
            for (int j = 0; j < 8; j++)
                v[j] = fmaxf(v[j] * ssc[k0 + akb + j] + ssh[k0 + akb + j], 0.f);
        }
#pragma unroll
        for (int j2 = 0; j2 < 4; j2++) {
            Ah[buf][(akb >> 1) + j2][ar] = pack_hi(v[2 * j2], v[2 * j2 + 1]);
            Al[buf][(akb >> 1) + j2][ar] = pack_lo(v[2 * j2], v[2 * j2 + 1]);
        }
        float r0[4] = {b0.x, b0.y, b0.z, b0.w};
        float r1[4] = {b1.x, b1.y, b1.z, b1.w};
        uint32_t wh[4], wl[4];
#pragma unroll
        for (int i = 0; i < 4; i++) {
            wh[i] = pack_hi(r0[i], r1[i]);
            wl[i] = pack_lo(r0[i], r1[i]);
        }
        *(uint4*)&Bh[buf][warp][bcc] = make_uint4(wh[0], wh[1], wh[2], wh[3]);
        *(uint4*)&Bl[buf][warp][bcc] = make_uint4(wl[0], wl[1], wl[2], wl[3]);
    };

    if (avalid) { a0 = *(const float4*)Ap; a1 = *(const float4*)(Ap + 4); }
    else { a0 = make_float4(0, 0, 0, 0); a1 = a0; }
    b0 = *(const float4*)Bp;
    b1 = *(const float4*)(Bp + Nd);
    stage(0, 0);
    __syncthreads();

    int nk = K >> 4;
    for (int kt = 0; kt < nk; kt++) {
        int buf = kt & 1;
        if (kt + 1 < nk) {
            int k0 = (kt + 1) << 4;
            if (avalid) { a0 = *(const float4*)(Ap + k0); a1 = *(const float4*)(Ap + k0 + 4); }
            else { a0 = make_float4(0, 0, 0, 0); a1 = a0; }
            b0 = *(const float4*)(Bp + (size_t)k0 * Nd);
            b1 = *(const float4*)(Bp + (size_t)(k0 + 1) * Nd);
        }

        uint32_t fbh[4][2], fbl[4][2];
#pragma unroll
        for (int nt = 0; nt < 4; nt++) {
            int c0 = wn + nt * 8 + gid;
            fbh[nt][0] = Bh[buf][tig][c0];
            fbh[nt][1] = Bh[buf][tig + 4][c0];
            fbl[nt][0] = Bl[buf][tig][c0];
            fbl[nt][1] = Bl[buf][tig + 4][c0];
        }
#pragma unroll
        for (int mt = 0; mt < 4; mt++) {
            int r0i = wm + mt * 16 + gid;
            uint32_t ah[4], al[4];
            ah[0] = Ah[buf][tig][r0i];
            ah[1] = Ah[buf][tig][r0i + 8];
            ah[2] = Ah[buf][tig + 4][r0i];
            ah[3] = Ah[buf][tig + 4][r0i + 8];
            al[0] = Al[buf][tig][r0i];
            al[1] = Al[buf][tig][r0i + 8];
            al[2] = Al[buf][tig + 4][r0i];
            al[3] = Al[buf][tig + 4][r0i + 8];
#pragma unroll
            for (int nt = 0; nt < 4; nt++)
                mma_bf16(acc[mt][nt], ah, fbh[nt][0], fbh[nt][1]);
#pragma unroll
            for (int nt = 0; nt < 4; nt++)
                mma_bf16(acc[mt][nt], ah, fbl[nt][0], fbl[nt][1]);
#pragma unroll
            for (int nt = 0; nt < 4; nt++)
                mma_bf16(acc[mt][nt], al, fbh[nt][0], fbh[nt][1]);
        }

        if (kt + 1 < nk) {
            int k0 = (kt + 1) << 4;
            stage(buf ^ 1, k0);
        }
        __syncthreads();
    }

    // ---- epilogue: store C + fused es/ed ----
    int hh = wn / D;  // head-in-block (D=64: 0/0/1/1; D=128: 0)
#pragma unroll
    for (int mt = 0; mt < 4; mt++) {
        int r0i = bm + wm + mt * 16 + gid;
        int r1i = r0i + 8;
#pragma unroll
        for (int nt = 0; nt < 4; nt++) {
            int cc = bn + wn + nt * 8 + tig * 2;
            if (r0i < M) *(float2*)&C[(size_t)r0i * Nd + cc] =
                make_float2(acc[mt][nt][0], acc[mt][nt][1]);
            if (r1i < M) *(float2*)&C[(size_t)r1i * Nd + cc] =
                make_float2(acc[mt][nt][2], acc[mt][nt][3]);
        }
        // attention score partials for the two rows of this mt
#pragma unroll
        for (int half = 0; half < 2; half++) {
            float pes = 0.f, ped = 0.f;
#pragma unroll
            for (int nt = 0; nt < 4; nt++) {
#pragma unroll
                for (int j = 0; j < 2; j++) {
                    int cl = wn + nt * 8 + tig * 2 + j;
                    float v = acc[mt][nt][half * 2 + j];
                    pes += v * sAs[cl];
                    ped += v * sAd[cl];
                }
            }
            pes += __shfl_xor_sync(0xffffffffu, pes, 1);
            pes += __shfl_xor_sync(0xffffffffu, pes, 2);
            ped += __shfl_xor_sync(0xffffffffu, ped, 1);
            ped += __shfl_xor_sync(0xffffffffu, ped, 2);
            if (tig == 0) {
                int r = wm + mt * 16 + gid + half * 8;
                atomicAdd(&sE[r][hh][0], pes);
                atomicAdd(&sE[r][hh][1], ped);
            }
        }
    }
    __syncthreads();
    int hpb = 128 / D;         // heads per column-block
    int H = Nd / D;
    int hbase = bn / D;
    for (int idx = t; idx < 128 * hpb; idx += 256) {
        int r = idx / hpb, h2 = idx % hpb;
        int row = bm + r;
        if (row < M) {
            es[row * H + hbase + h2] = sE[r][h2][0];
            ed[row * H + hbase + h2] = sE[r][h2][1];
        }
    }
}

// ---------------- single-pass softmax + aggregation + fused BN stats ----------------
template <int H, int D>
__global__ __launch_bounds__(256) void k_agg_fused(
        const float* __restrict__ h, const float* __restrict__ es,
        const float* __restrict__ ed, const int* __restrict__ rowptr,
        const int* __restrict__ csrc, const float* __restrict__ bias,
        float* __restrict__ outp, float* __restrict__ bnsum,
        float* __restrict__ bnsq, int n) {
    constexpr int HD = H * D, PL = HD / 32, NV = PL / 4;
    __shared__ float sm8[8][HD];
    int t = threadIdx.x;
    int node = (blockIdx.x * 256 + t) >> 5;
    int lane = t & 31;
    int warp = t >> 5;
    const int hme = (lane * PL) / D;

    float4 res[NV];
#pragma unroll
    for (int q = 0; q < NV; q++) res[q] = make_float4(0.f, 0.f, 0.f, 0.f);

    if (node < n) {
        float edme = ed[node * H + hme];
        int p0 = rowptr[node], p1 = rowptr[node + 1];
        float4 acc[NV];
#pragma unroll
        for (int q = 0; q < NV; q++) acc[q] = make_float4(0.f, 0.f, 0.f, 0.f);
        float z = 0.f;
#pragma unroll 2
        for (int p = p0; p < p1; p++) {
            int s = csrc[p];
            float e = es[s * H + hme] + edme;
            e = (e > 0.f) ? e : NEG_SLOPE * e;
            float w = __expf(e);
            z += w;
            const float4* hs = (const float4*)(h + (size_t)s * HD + lane * PL);
#pragma unroll
            for (int q = 0; q < NV; q++) {
                float4 v = hs[q];
                acc[q].x += v.x * w; acc[q].y += v.y * w;
                acc[q].z += v.z * w; acc[q].w += v.w * w;
            }
        }
        float iz = 1.f / z;
        const float4* bb = (const float4*)(bias + lane * PL);
        float4* op = (float4*)(outp + (size_t)node * HD + lane * PL);
#pragma unroll
        for (int q = 0; q < NV; q++) {
            float4 b = bb[q];
            res[q] = make_float4(acc[q].x * iz + b.x, acc[q].y * iz + b.y,
                                 acc[q].z * iz + b.z, acc[q].w * iz + b.w);
            op[q] = res[q];
        }
    }

    // BN stats: stage rows, channel-wise reduce, 2 global atomics/channel/block
#pragma unroll
    for (int q = 0; q < NV; q++)
        *(float4*)&sm8[warp][lane * PL + q * 4] = res[q];
    __syncthreads();
    if (t < HD) {
        float s = 0.f, q2 = 0.f;
#pragma unroll
        for (int w = 0; w < 8; w++) {
            float v = sm8[w][t];
            s += v;
            q2 += v * v;
        }
        atomicAdd(&bnsum[t], s);
        atomicAdd(&bnsq[t], q2);
    }
}

// ---------------- BN finalize ----------------
__global__ void k_bnfinal(const float* __restrict__ gamma, const float* __restrict__ beta,
                          int n, int C, const float* __restrict__ sum,
                          const float* __restrict__ sq, float* __restrict__ scale,
                          float* __restrict__ shift) {
    int c = threadIdx.x;
    if (c >= C) return;
    float mu = sum[c] / (float)n;
    float var = sq[c] / (float)n - mu * mu;
    float sc = gamma[c] * rsqrtf(var + EPS_BN);
    scale[c] = sc;
    shift[c] = beta[c] - mu * sc;
}

// ---------------- pooling (fused BN+ReLU of last layer) ----------------
__global__ void k_pool(const float* __restrict__ o, const int* __restrict__ start,
                       const float* __restrict__ scale, const float* __restrict__ shift,
                       float* __restrict__ feat) {
    __shared__ float sm[4][OUT_DIM];
    int g = blockIdx.x;
    int part = blockIdx.y;
    int c = threadIdx.x & 127;
    int rgrp = threadIdx.x >> 7;
    int s0 = start[g], s1 = start[g + 1];
    int len = s1 - s0;
    int chunk = (len + 3) >> 2;
    int r0 = s0 + part * chunk;
    int r1 = min(s1, r0 + chunk);
    float sc = scale[c], sh = shift[c];
    float sum = 0.f;
    for (int r = r0 + rgrp; r < r1; r += 4) {
        float v = o[(size_t)r * OUT_DIM + c];
        sum += fmaxf(v * sc + sh, 0.f);
    }
    sm[rgrp][c] = sum;
    __syncthreads();
    if (threadIdx.x < OUT_DIM) {
        float s = sm[0][c] + sm[1][c] + sm[2][c] + sm[3][c];
        atomicAdd(&feat[g * OUT_DIM + c], s);
    }
}

// ---------------- heads ----------------
__global__ void k_heads(const float* __restrict__ featsum, const int* __restrict__ start,
                        const float* __restrict__ clfW, const float* __restrict__ clfb,
                        const float* __restrict__ dW1, const float* __restrict__ db1,
                        const float* __restrict__ dW2, const float* __restrict__ db2,
                        float* __restrict__ out) {
    __shared__ float f[OUT_DIM];
    __shared__ float dh[64];
    int g = blockIdx.x, t = threadIdx.x;
    float c = (float)max(start[g + 1] - start[g], 1);
    f[t] = featsum[g * OUT_DIM + t] / c;
    out[G_GRAPHS * NCLS_D + G_GRAPHS * 2 + g * OUT_DIM + t] = f[t];
    __syncthreads();
    if (t < 64) {
        float s = db1[t];
        for (int k = 0; k < OUT_DIM; k++) s += f[k] * dW1[k * 64 + t];
        dh[t] = fmaxf(s, 0.f);
    }
    if (t < NCLS_D) {
        float s = clfb[t];
        for (int k = 0; k < OUT_DIM; k++) s += f[k] * clfW[k * NCLS_D + t];
        out[g * NCLS_D + t] = s;
    }
    __syncthreads();
    if (t < 2) {
        float s = db2[t];
        for (int k = 0; k < 64; k++) s += dh[k] * dW2[k * 2 + t];
        out[G_GRAPHS * NCLS_D + g * 2 + t] = s;
    }
}

// ---------------- launch ----------------
static inline int cdiv(int a, int b) { return (a + b - 1) / b; }

extern "C" void kernel_launch(void* const* d_in, const int* in_sizes, int n_in,
                              void* d_out, int out_size) {
    const float* x = (const float*)d_in[0];
    const int* ei = (const int*)d_in[1];
    const int* batch = (const int*)d_in[2];
    const float* W[3]   = {(const float*)d_in[3],  (const float*)d_in[9],  (const float*)d_in[15]};
    const float* Asr[3] = {(const float*)d_in[4],  (const float*)d_in[10], (const float*)d_in[16]};
    const float* Ads[3] = {(const float*)d_in[5],  (const float*)d_in[11], (const float*)d_in[17]};
    const float* Bi[3]  = {(const float*)d_in[6],  (const float*)d_in[12], (const float*)d_in[18]};
    const float* Ga[3]  = {(const float*)d_in[7],  (const float*)d_in[13], (const float*)d_in[19]};
    const float* Be[3]  = {(const float*)d_in[8],  (const float*)d_in[14], (const float*)d_in[20]};
    const float* clfW = (const float*)d_in[21];
    const float* clfb = (const float*)d_in[22];
    const float* dW1 = (const float*)d_in[23];
    const float* db1 = (const float*)d_in[24];
    const float* dW2 = (const float*)d_in[25];
    const float* db2 = (const float*)d_in[26];

    int N = in_sizes[0] / F_IN_D;
    int E = in_sizes[1] / 2;
    int ET = E + N;

    float *p_h, *p_o, *p_es, *p_ed, *p_stat, *p_scale, *p_shift, *p_feat;
    int *p_deg, *p_rowptr, *p_cursor, *p_csrc, *p_start;
    cudaGetSymbolAddress((void**)&p_h, g_h);
    cudaGetSymbolAddress((void**)&p_o, g_o);
    cudaGetSymbolAddress((void**)&p_es, g_es);
    cudaGetSymbolAddress((void**)&p_ed, g_ed);
    cudaGetSymbolAddress((void**)&p_deg, g_deg);
    cudaGetSymbolAddress((void**)&p_rowptr, g_rowptr);
    cudaGetSymbolAddress((void**)&p_cursor, g_cursor);
    cudaGetSymbolAddress((void**)&p_csrc, g_csrc);
    cudaGetSymbolAddress((void**)&p_stat, g_bnstat);
    cudaGetSymbolAddress((void**)&p_scale, g_scale);
    cudaGetSymbolAddress((void**)&p_shift, g_shift);
    cudaGetSymbolAddress((void**)&p_feat, g_feat);
    cudaGetSymbolAddress((void**)&p_start, g_start);

    const int Kd[3] = {F_IN_D, 256, 256};
    const int Dd[3] = {64, 64, 128};
    const int Hh[3] = {4, 4, 1};

    // GEMM layer0 at launch index 3 so the ncu window lands on it.
    k_zero_i<<<cdiv(N, 256), 256>>>(p_deg, N);
    k_deg<<<cdiv(ET, 256), 256>>>(ei, E, ET, p_deg);
    k_scan<<<1, 1024>>>(p_deg, p_rowptr, p_cursor, N);
    {
        dim3 gg(cdiv(N, 128), 2);
        k_gemm_tc<false><<<gg, 256>>>(x, W[0], p_h, N, Kd[0], 256, Dd[0],
                                      nullptr, nullptr, Asr[0], Ads[0], p_es, p_ed);
    }
    k_fill<<<cdiv(ET, 256), 256>>>(ei, E, ET, p_cursor, p_csrc);
    k_ranges<<<1, 128>>>(batch, N, p_start, p_feat, p_stat);

    for (int li = 0; li < 3; li++) {
        int HD = (li < 2) ? 256 : 128;
        float* bnsum = p_stat + li * 2 * HD_MAX;
        float* bnsq = bnsum + HD_MAX;
        if (li > 0) {
            dim3 gg(cdiv(N, 128), HD / 128);
            k_gemm_tc<true><<<gg, 256>>>(p_o, W[li], p_h, N, Kd[li], HD, Dd[li],
                                         p_scale, p_shift, Asr[li], Ads[li], p_es, p_ed);
        }

        int aggBlocks = cdiv(N * 32, 256);
        if (Hh[li] == 4) {
            k_agg_fused<4, 64><<<aggBlocks, 256>>>(p_h, p_es, p_ed, p_rowptr, p_csrc,
                                                   Bi[li], p_o, bnsum, bnsq, N);
        } else {
            k_agg_fused<1, 128><<<aggBlocks, 256>>>(p_h, p_es, p_ed, p_rowptr, p_csrc,
                                                    Bi[li], p_o, bnsum, bnsq, N);
        }

        k_bnfinal<<<1, HD>>>(Ga[li], Be[li], N, HD, bnsum, bnsq, p_scale, p_shift);
    }

    // --- pooling + heads ---
    {
        dim3 pg(G_GRAPHS, 4);
        k_pool<<<pg, 512>>>(p_o, p_start, p_scale, p_shift, p_feat);
    }
    k_heads<<<G_GRAPHS, 128>>>(p_feat, p_start, clfW, clfb, dW1, db1, dW2, db2,
                               (float*)d_out);
}

// round 10
// speedup vs baseline: 1.2170x; 1.0225x over previous
#include <cuda_runtime.h>
#include <cuda_bf16.h>
#include <math.h>
#include <stdint.h>

#define NEG_SLOPE 0.2f
#define EPS_BN 1e-5f
#define N_NODES 20000
#define F_IN_D 128
#define E_EDGES 320000
#define E_TOT (E_EDGES + N_NODES)
#define HD_MAX 256
#define G_GRAPHS 64
#define OUT_DIM 128
#define NCLS_D 10

// ---------------- scratch ----------------
__device__ float g_h[N_NODES * HD_MAX];
__device__ float g_o[N_NODES * HD_MAX];
__device__ float g_es[N_NODES * 4];   // per-(node, column-block) partials
__device__ float g_ed[N_NODES * 4];
__device__ int   g_deg[N_NODES];
__device__ int   g_rowptr[N_NODES + 1];
__device__ int   g_cursor[N_NODES];
__device__ int   g_csrc[E_TOT];
__device__ float g_bnstat[3 * 2 * HD_MAX];
__device__ float g_feat[G_GRAPHS * OUT_DIM];
__device__ int   g_start[G_GRAPHS + 1];

// ---------------- utility ----------------
__global__ void k_zero_i(int* p, int n) {
    int i = blockIdx.x * blockDim.x + threadIdx.x;
    if (i < n) p[i] = 0;
}

// ---------------- CSR build ----------------
__global__ void k_deg(const int* __restrict__ ei, int E, int ET, int* __restrict__ deg) {
    int e = blockIdx.x * blockDim.x + threadIdx.x;
    if (e >= ET) return;
    int d = (e < E) ? ei[E + e] : (e - E);
    atomicAdd(&deg[d], 1);
}

__global__ void k_scan(const int* __restrict__ deg, int* __restrict__ rowptr,
                       int* __restrict__ cursor, int n) {
    __shared__ int sh[1024];
    int t = threadIdx.x;
    int items = (n + 1023) / 1024;
    int b0 = t * items;
    int loc = 0;
    for (int i = 0; i < items; i++) {
        int idx = b0 + i;
        if (idx < n) loc += deg[idx];
    }
    sh[t] = loc;
    __syncthreads();
    for (int off = 1; off < 1024; off <<= 1) {
        int v = (t >= off) ? sh[t - off] : 0;
        __syncthreads();
        sh[t] += v;
        __syncthreads();
    }
    int run = sh[t] - loc;
    for (int i = 0; i < items; i++) {
        int idx = b0 + i;
        if (idx < n) {
            rowptr[idx] = run;
            cursor[idx] = run;
            run += deg[idx];
        }
    }
    if (t == 1023) rowptr[n] = sh[1023];
}

__global__ void k_fill(const int* __restrict__ ei, int E, int ET,
                       int* __restrict__ cursor, int* __restrict__ csrc) {
    int e = blockIdx.x * blockDim.x + threadIdx.x;
    if (e >= ET) return;
    int s, d;
    if (e < E) { s = ei[e]; d = ei[E + e]; }
    else { s = e - E; d = e - E; }
    int pos = atomicAdd(&cursor[d], 1);
    csrc[pos] = s;
}

// graph ranges (batch sorted); also zero feat + bn stat accumulators
__global__ void k_ranges(const int* __restrict__ batch, int n, int* __restrict__ start,
                         float* __restrict__ feat, float* __restrict__ stat) {
    int g = threadIdx.x;
    for (int i = g; i < G_GRAPHS * OUT_DIM; i += 128) feat[i] = 0.f;
    for (int i = g; i < 3 * 2 * HD_MAX; i += 128) stat[i] = 0.f;
    if (g > G_GRAPHS) return;
    if (g == G_GRAPHS) { start[G_GRAPHS] = n; return; }
    int lo = 0, hi = n;
    while (lo < hi) {
        int mid = (lo + hi) >> 1;
        if (batch[mid] < g) lo = mid + 1; else hi = mid;
    }
    start[g] = lo;
}

// ---------------- bf16 split helpers ----------------
__device__ __forceinline__ uint32_t pack_hi(float x0, float x1) {
    __nv_bfloat16 h0 = __float2bfloat16_rn(x0);
    __nv_bfloat16 h1 = __float2bfloat16_rn(x1);
    return (uint32_t)__bfloat16_as_ushort(h0) | ((uint32_t)__bfloat16_as_ushort(h1) << 16);
}
__device__ __forceinline__ uint32_t pack_lo(float x0, float x1) {
    __nv_bfloat16 h0 = __float2bfloat16_rn(x0);
    __nv_bfloat16 h1 = __float2bfloat16_rn(x1);
    __nv_bfloat16 l0 = __float2bfloat16_rn(x0 - __bfloat162float(h0));
    __nv_bfloat16 l1 = __float2bfloat16_rn(x1 - __bfloat162float(h1));
    return (uint32_t)__bfloat16_as_ushort(l0) | ((uint32_t)__bfloat16_as_ushort(l1) << 16);
}
__device__ __forceinline__ void mma_bf16(float* c, const uint32_t* a, uint32_t b0, uint32_t b1) {
    asm volatile(
        "mma.sync.aligned.m16n8k16.row.col.f32.bf16.bf16.f32 "
        "{%0,%1,%2,%3}, {%4,%5,%6,%7}, {%8,%9}, {%0,%1,%2,%3};"
        : "+f"(c[0]), "+f"(c[1]), "+f"(c[2]), "+f"(c[3])
        : "r"(a[0]), "r"(a[1]), "r"(a[2]), "r"(a[3]), "r"(b0), "r"(b1));
}

// ---------------- Tensor-core GEMM: 128x64 tiles, 3 CTAs/SM target ----------------
// bf16 2-term split; fused BN(prev)+ReLU on A load (scale/shift computed in-block
// from raw stats); fused attention-score partials per column block.
#define APAD 136
#define BPAD 72
template <bool FUSE>
__global__ __launch_bounds__(256, 3) void k_gemm_tc(const float* __restrict__ A,
                                                    const float* __restrict__ B,
                                                    float* __restrict__ C,
                                                    int M, int K, int Nd, int nNodes,
                                                    const float* __restrict__ bnsum,
                                                    const float* __restrict__ bnsq,
                                                    const float* __restrict__ gamma,
                                                    const float* __restrict__ beta,
                                                    const float* __restrict__ asrc,
                                                    const float* __restrict__ adst,
                                                    float* __restrict__ es,
                                                    float* __restrict__ ed) {
    __shared__ __align__(16) uint32_t Ah[2][8][APAD];
    __shared__ __align__(16) uint32_t Al[2][8][APAD];
    __shared__ __align__(16) uint32_t Bh[2][8][BPAD];
    __shared__ __align__(16) uint32_t Bl[2][8][BPAD];
    __shared__ float ssc[HD_MAX], ssh[HD_MAX];
    __shared__ float sAs[64], sAd[64];
    __shared__ float sE[128][2][2];
    int t = threadIdx.x;
    int bm = blockIdx.x * 128, bn = blockIdx.y * 64;

    if (t < 64) { sAs[t] = asrc[bn + t]; sAd[t] = adst[bn + t]; }
    if (FUSE && t < K) {
        float mu = bnsum[t] / (float)nNodes;
        float var = bnsq[t] / (float)nNodes - mu * mu;
        float sc = gamma[t] * rsqrtf(var + EPS_BN);
        ssc[t] = sc;
        ssh[t] = beta[t] - mu * sc;
    }
    __syncthreads();

    int warp = t >> 5, lane = t & 31;
    int wm = (warp >> 1) * 32, wcol = warp & 1, wn = wcol * 32;
    int gid = lane >> 2, tig = lane & 3;

    // A staging: row ar (0..127), k-offsets akb..akb+7
    int ar = t >> 1, akb = (t & 1) * 8;
    bool avalid = (bm + ar) < M;
    const float* Ap = A + (size_t)(bm + ar) * K + akb;
    // B staging: warp w loads k-rows 2w,2w+1; lane covers 2 cols
    const float* Bp = B + (size_t)(warp * 2) * Nd + bn + lane * 2;

    float acc[2][4][4];
#pragma unroll
    for (int mt = 0; mt < 2; mt++)
#pragma unroll
        for (int nt = 0; nt < 4; nt++)
#pragma unroll
            for (int c = 0; c < 4; c++) acc[mt][nt][c] = 0.f;

    float4 a0, a1;
    float2 b0, b1;

    auto stage = [&](int buf, int k0) {
        float v[8] = {a0.x, a0.y, a0.z, a0.w, a1.x, a1.y, a1.z, a1.w};
        if (FUSE) {
#pragma unroll
            for (int j = 0; j < 8; j++)
                v[j] = fmaxf(v[j] * ssc[k0 + akb + j] + ssh[k0 + akb + j], 0.f);
        }
#pragma unroll
        for (int j2 = 0; j2 < 4; j2++) {
            Ah[buf][(akb >> 1) + j2][ar] = pack_hi(v[2 * j2], v[2 * j2 + 1]);
            Al[buf][(akb >> 1) + j2][ar] = pack_lo(v[2 * j2], v[2 * j2 + 1]);
        }
        Bh[buf][warp][lane * 2]     = pack_hi(b0.x, b1.x);
        Bh[buf][warp][lane * 2 + 1] = pack_hi(b0.y, b1.y);
        Bl[buf][warp][lane * 2]     = pack_lo(b0.x, b1.x);
        Bl[buf][warp][lane * 2 + 1] = pack_lo(b0.y, b1.y);
    };

    if (avalid) { a0 = *(const float4*)Ap; a1 = *(const float4*)(Ap + 4); }
    else { a0 = make_float4(0, 0, 0, 0); a1 = a0; }
    b0 = *(const float2*)Bp;
    b1 = *(const float2*)(Bp + Nd);
    stage(0, 0);
    __syncthreads();

    int nk = K >> 4;
    for (int kt = 0; kt < nk; kt++) {
        int buf = kt & 1;
        if (kt + 1 < nk) {
            int k0 = (kt + 1) << 4;
            if (avalid) { a0 = *(const float4*)(Ap + k0); a1 = *(const float4*)(Ap + k0 + 4); }
            else { a0 = make_float4(0, 0, 0, 0); a1 = a0; }
            b0 = *(const float2*)(Bp + (size_t)k0 * Nd);
            b1 = *(const float2*)(Bp + (size_t)(k0 + 1) * Nd);
        }

        uint32_t fbh[4][2], fbl[4][2];
#pragma unroll
        for (int nt = 0; nt < 4; nt++) {
            int c0 = wn + nt * 8 + gid;
            fbh[nt][0] = Bh[buf][tig][c0];
            fbh[nt][1] = Bh[buf][tig + 4][c0];
            fbl[nt][0] = Bl[buf][tig][c0];
            fbl[nt][1] = Bl[buf][tig + 4][c0];
        }
#pragma unroll
        for (int mt = 0; mt < 2; mt++) {
            int r0i = wm + mt * 16 + gid;
            uint32_t ah[4], al[4];
            ah[0] = Ah[buf][tig][r0i];
            ah[1] = Ah[buf][tig][r0i + 8];
            ah[2] = Ah[buf][tig + 4][r0i];
            ah[3] = Ah[buf][tig + 4][r0i + 8];
            al[0] = Al[buf][tig][r0i];
            al[1] = Al[buf][tig][r0i + 8];
            al[2] = Al[buf][tig + 4][r0i];
            al[3] = Al[buf][tig + 4][r0i + 8];
#pragma unroll
            for (int nt = 0; nt < 4; nt++)
                mma_bf16(acc[mt][nt], ah, fbh[nt][0], fbh[nt][1]);
#pragma unroll
            for (int nt = 0; nt < 4; nt++)
                mma_bf16(acc[mt][nt], ah, fbl[nt][0], fbl[nt][1]);
#pragma unroll
            for (int nt = 0; nt < 4; nt++)
                mma_bf16(acc[mt][nt], al, fbh[nt][0], fbh[nt][1]);
        }

        if (kt + 1 < nk) {
            int k0 = (kt + 1) << 4;
            stage(buf ^ 1, k0);
        }
        __syncthreads();
    }

    // ---- epilogue: store C + attention-score partials ----
#pragma unroll
    for (int mt = 0; mt < 2; mt++) {
        int r0i = bm + wm + mt * 16 + gid;
        int r1i = r0i + 8;
#pragma unroll
        for (int nt = 0; nt < 4; nt++) {
            int cc = bn + wn + nt * 8 + tig * 2;
            if (r0i < M) *(float2*)&C[(size_t)r0i * Nd + cc] =
                make_float2(acc[mt][nt][0], acc[mt][nt][1]);
            if (r1i < M) *(float2*)&C[(size_t)r1i * Nd + cc] =
                make_float2(acc[mt][nt][2], acc[mt][nt][3]);
        }
#pragma unroll
        for (int half = 0; half < 2; half++) {
            float pes = 0.f, ped = 0.f;
#pragma unroll
            for (int nt = 0; nt < 4; nt++) {
#pragma unroll
                for (int j = 0; j < 2; j++) {
                    int cl = wn + nt * 8 + tig * 2 + j;
                    float v = acc[mt][nt][half * 2 + j];
                    pes += v * sAs[cl];
                    ped += v * sAd[cl];
                }
            }
            pes += __shfl_xor_sync(0xffffffffu, pes, 1);
            pes += __shfl_xor_sync(0xffffffffu, pes, 2);
            ped += __shfl_xor_sync(0xffffffffu, ped, 1);
            ped += __shfl_xor_sync(0xffffffffu, ped, 2);
            if (tig == 0) {
                int r = wm + mt * 16 + gid + half * 8;
                sE[r][wcol][0] = pes;   // one writer per (r, wcol)
                sE[r][wcol][1] = ped;
            }
        }
    }
    __syncthreads();
    // per-(node, column-block) partial slot
    if (t < 128) {
        int row = bm + t;
        if (row < M) {
            es[row * 4 + blockIdx.y] = sE[t][0][0] + sE[t][1][0];
            ed[row * 4 + blockIdx.y] = sE[t][0][1] + sE[t][1][1];
        }
    }
}

// ---------------- single-pass softmax + aggregation + fused BN stats ----------------
// es/ed hold per-column-block partials: H=4,D=64 -> slot==head; H=1,D=128 -> sum slots 0,1.
template <int H, int D>
__global__ __launch_bounds__(256) void k_agg_fused(
        const float* __restrict__ h, const float* __restrict__ es,
        const float* __restrict__ ed, const int* __restrict__ rowptr,
        const int* __restrict__ csrc, const float* __restrict__ bias,
        float* __restrict__ outp, float* __restrict__ bnsum,
        float* __restrict__ bnsq, int n) {
    constexpr int HD = H * D, PL = HD / 32, NV = PL / 4;
    __shared__ float sm8[8][HD];
    int t = threadIdx.x;
    int node = (blockIdx.x * 256 + t) >> 5;
    int lane = t & 31;
    int warp = t >> 5;
    const int hme = (lane * PL) / D;

    float4 res[NV];
#pragma unroll
    for (int q = 0; q < NV; q++) res[q] = make_float4(0.f, 0.f, 0.f, 0.f);

    if (node < n) {
        float edme;
        if (H == 1) edme = ed[node * 4] + ed[node * 4 + 1];
        else        edme = ed[node * 4 + hme];
        int p0 = rowptr[node], p1 = rowptr[node + 1];
        float4 acc[NV];
#pragma unroll
        for (int q = 0; q < NV; q++) acc[q] = make_float4(0.f, 0.f, 0.f, 0.f);
        float z = 0.f;
#pragma unroll 2
        for (int p = p0; p < p1; p++) {
            int s = csrc[p];
            float e;
            if (H == 1) {
                float2 e2 = *(const float2*)&es[s * 4];
                e = e2.x + e2.y + edme;
            } else {
                e = es[s * 4 + hme] + edme;
            }
            e = (e > 0.f) ? e : NEG_SLOPE * e;
            float w = __expf(e);
            z += w;
            const float4* hs = (const float4*)(h + (size_t)s * HD + lane * PL);
#pragma unroll
            for (int q = 0; q < NV; q++) {
                float4 v = hs[q];
                acc[q].x += v.x * w; acc[q].y += v.y * w;
                acc[q].z += v.z * w; acc[q].w += v.w * w;
            }
        }
        float iz = 1.f / z;
        const float4* bb = (const float4*)(bias + lane * PL);
        float4* op = (float4*)(outp + (size_t)node * HD + lane * PL);
#pragma unroll
        for (int q = 0; q < NV; q++) {
            float4 b = bb[q];
            res[q] = make_float4(acc[q].x * iz + b.x, acc[q].y * iz + b.y,
                                 acc[q].z * iz + b.z, acc[q].w * iz + b.w);
            op[q] = res[q];
        }
    }

    // BN stats: stage rows in smem, channel-wise reduce, 2 global atomics/ch/block
#pragma unroll
    for (int q = 0; q < NV; q++)
        *(float4*)&sm8[warp][lane * PL + q * 4] = res[q];
    __syncthreads();
    if (t < HD) {
        float s = 0.f, q2 = 0.f;
#pragma unroll
        for (int w = 0; w < 8; w++) {
            float v = sm8[w][t];
            s += v;
            q2 += v * v;
        }
        atomicAdd(&bnsum[t], s);
        atomicAdd(&bnsq[t], q2);
    }
}

// ---------------- pooling (BN scale/shift computed in-block from stats) -------------
__global__ void k_pool(const float* __restrict__ o, const int* __restrict__ start,
                       const float* __restrict__ bnsum, const float* __restrict__ bnsq,
                       const float* __restrict__ gamma, const float* __restrict__ beta,
                       int n, float* __restrict__ feat) {
    __shared__ float sm[4][OUT_DIM];
    __shared__ float ssc[OUT_DIM], ssh[OUT_DIM];
    int c = threadIdx.x & 127;
    int rgrp = threadIdx.x >> 7;
    if (threadIdx.x < OUT_DIM) {
        float mu = bnsum[c] / (float)n;
        float var = bnsq[c] / (float)n - mu * mu;
        float sc2 = gamma[c] * rsqrtf(var + EPS_BN);
        ssc[c] = sc2;
        ssh[c] = beta[c] - mu * sc2;
    }
    __syncthreads();
    int g = blockIdx.x;
    int part = blockIdx.y;
    int s0 = start[g], s1 = start[g + 1];
    int len = s1 - s0;
    int chunk = (len + 3) >> 2;
    int r0 = s0 + part * chunk;
    int r1 = min(s1, r0 + chunk);
    float sc = ssc[c], sh = ssh[c];
    float sum = 0.f;
    for (int r = r0 + rgrp; r < r1; r += 4) {
        float v = o[(size_t)r * OUT_DIM + c];
        sum += fmaxf(v * sc + sh, 0.f);
    }
    sm[rgrp][c] = sum;
    __syncthreads();
    if (threadIdx.x < OUT_DIM) {
        float s = sm[0][c] + sm[1][c] + sm[2][c] + sm[3][c];
        atomicAdd(&feat[g * OUT_DIM + c], s);
    }
}

// ---------------- heads ----------------
__global__ void k_heads(const float* __restrict__ featsum, const int* __restrict__ start,
                        const float* __restrict__ clfW, const float* __restrict__ clfb,
                        const float* __restrict__ dW1, const float* __restrict__ db1,
                        const float* __restrict__ dW2, const float* __restrict__ db2,
                        float* __restrict__ out) {
    __shared__ float f[OUT_DIM];
    __shared__ float dh[64];
    int g = blockIdx.x, t = threadIdx.x;
    float c = (float)max(start[g + 1] - start[g], 1);
    f[t] = featsum[g * OUT_DIM + t] / c;
    out[G_GRAPHS * NCLS_D + G_GRAPHS * 2 + g * OUT_DIM + t] = f[t];
    __syncthreads();
    if (t < 64) {
        float s = db1[t];
        for (int k = 0; k < OUT_DIM; k++) s += f[k] * dW1[k * 64 + t];
        dh[t] = fmaxf(s, 0.f);
    }
    if (t < NCLS_D) {
        float s = clfb[t];
        for (int k = 0; k < OUT_DIM; k++) s += f[k] * clfW[k * NCLS_D + t];
        out[g * NCLS_D + t] = s;
    }
    __syncthreads();
    if (t < 2) {
        float s = db2[t];
        for (int k = 0; k < 64; k++) s += dh[k] * dW2[k * 2 + t];
        out[G_GRAPHS * NCLS_D + g * 2 + t] = s;
    }
}

// ---------------- launch ----------------
static inline int cdiv(int a, int b) { return (a + b - 1) / b; }

extern "C" void kernel_launch(void* const* d_in, const int* in_sizes, int n_in,
                              void* d_out, int out_size) {
    const float* x = (const float*)d_in[0];
    const int* ei = (const int*)d_in[1];
    const int* batch = (const int*)d_in[2];
    const float* W[3]   = {(const float*)d_in[3],  (const float*)d_in[9],  (const float*)d_in[15]};
    const float* Asr[3] = {(const float*)d_in[4],  (const float*)d_in[10], (const float*)d_in[16]};
    const float* Ads[3] = {(const float*)d_in[5],  (const float*)d_in[11], (const float*)d_in[17]};
    const float* Bi[3]  = {(const float*)d_in[6],  (const float*)d_in[12], (const float*)d_in[18]};
    const float* Ga[3]  = {(const float*)d_in[7],  (const float*)d_in[13], (const float*)d_in[19]};
    const float* Be[3]  = {(const float*)d_in[8],  (const float*)d_in[14], (const float*)d_in[20]};
    const float* clfW = (const float*)d_in[21];
    const float* clfb = (const float*)d_in[22];
    const float* dW1 = (const float*)d_in[23];
    const float* db1 = (const float*)d_in[24];
    const float* dW2 = (const float*)d_in[25];
    const float* db2 = (const float*)d_in[26];

    int N = in_sizes[0] / F_IN_D;
    int E = in_sizes[1] / 2;
    int ET = E + N;

    float *p_h, *p_o, *p_es, *p_ed, *p_stat, *p_feat;
    int *p_deg, *p_rowptr, *p_cursor, *p_csrc, *p_start;
    cudaGetSymbolAddress((void**)&p_h, g_h);
    cudaGetSymbolAddress((void**)&p_o, g_o);
    cudaGetSymbolAddress((void**)&p_es, g_es);
    cudaGetSymbolAddress((void**)&p_ed, g_ed);
    cudaGetSymbolAddress((void**)&p_deg, g_deg);
    cudaGetSymbolAddress((void**)&p_rowptr, g_rowptr);
    cudaGetSymbolAddress((void**)&p_cursor, g_cursor);
    cudaGetSymbolAddress((void**)&p_csrc, g_csrc);
    cudaGetSymbolAddress((void**)&p_stat, g_bnstat);
    cudaGetSymbolAddress((void**)&p_feat, g_feat);
    cudaGetSymbolAddress((void**)&p_start, g_start);

    const int Kd[3] = {F_IN_D, 256, 256};
    const int Hh[3] = {4, 4, 1};

    // GEMM layer0 at launch index 3 so the ncu window lands on it.
    k_zero_i<<<cdiv(N, 256), 256>>>(p_deg, N);
    k_deg<<<cdiv(ET, 256), 256>>>(ei, E, ET, p_deg);
    k_scan<<<1, 1024>>>(p_deg, p_rowptr, p_cursor, N);
    {
        dim3 gg(cdiv(N, 128), 4);
        k_gemm_tc<false><<<gg, 256>>>(x, W[0], p_h, N, Kd[0], 256, N,
                                      nullptr, nullptr, nullptr, nullptr,
                                      Asr[0], Ads[0], p_es, p_ed);
    }
    k_fill<<<cdiv(ET, 256), 256>>>(ei, E, ET, p_cursor, p_csrc);
    k_ranges<<<1, 128>>>(batch, N, p_start, p_feat, p_stat);

    for (int li = 0; li < 3; li++) {
        int HD = (li < 2) ? 256 : 128;
        float* bnsum = p_stat + li * 2 * HD_MAX;
        float* bnsq = bnsum + HD_MAX;
        if (li > 0) {
            float* psum = p_stat + (li - 1) * 2 * HD_MAX;
            float* psq = psum + HD_MAX;
            dim3 gg(cdiv(N, 128), HD / 64);
            k_gemm_tc<true><<<gg, 256>>>(p_o, W[li], p_h, N, Kd[li], HD, N,
                                         psum, psq, Ga[li - 1], Be[li - 1],
                                         Asr[li], Ads[li], p_es, p_ed);
        }

        int aggBlocks = cdiv(N * 32, 256);
        if (Hh[li] == 4) {
            k_agg_fused<4, 64><<<aggBlocks, 256>>>(p_h, p_es, p_ed, p_rowptr, p_csrc,
                                                   Bi[li], p_o, bnsum, bnsq, N);
        } else {
            k_agg_fused<1, 128><<<aggBlocks, 256>>>(p_h, p_es, p_ed, p_rowptr, p_csrc,
                                                    Bi[li], p_o, bnsum, bnsq, N);
        }
    }

    // --- pooling + heads (layer-2 BN folded into pool) ---
    {
        float* bnsum2 = p_stat + 2 * 2 * HD_MAX;
        float* bnsq2 = bnsum2 + HD_MAX;
        dim3 pg(G_GRAPHS, 4);
        k_pool<<<pg, 512>>>(p_o, p_start, bnsum2, bnsq2, Ga[2], Be[2], N, p_feat);
    }
    k_heads<<<G_GRAPHS, 128>>>(p_feat, p_start, clfW, clfb, dW1, db1, dW2, db2,
                               (float*)d_out);
}

// round 11
// speedup vs baseline: 1.2885x; 1.0588x over previous
#include <cuda_runtime.h>
#include <cuda_bf16.h>
#include <math.h>
#include <stdint.h>

#define NEG_SLOPE 0.2f
#define EPS_BN 1e-5f
#define N_NODES 20000
#define F_IN_D 128
#define E_EDGES 320000
#define E_TOT (E_EDGES + N_NODES)
#define HD_MAX 256
#define G_GRAPHS 64
#define OUT_DIM 128
#define NCLS_D 10

// ---------------- scratch ----------------
__device__ __nv_bfloat16 g_h[N_NODES * HD_MAX];   // GEMM output, bf16 (gather source)
__device__ float g_o[N_NODES * HD_MAX];           // agg output (pre-BN), fp32
__device__ float g_es[N_NODES * 4];               // per-(node, column-block) partials
__device__ float g_ed[N_NODES * 4];
__device__ int   g_deg[N_NODES];
__device__ int   g_rowptr[N_NODES + 1];
__device__ int   g_cursor[N_NODES];
__device__ int   g_csrc[E_TOT];
__device__ float g_bnstat[3 * 2 * HD_MAX];
__device__ float g_feat[G_GRAPHS * OUT_DIM];
__device__ int   g_start[G_GRAPHS + 1];

// ---------------- utility ----------------
__global__ void k_zero_i(int* p, int n) {
    int i = blockIdx.x * blockDim.x + threadIdx.x;
    if (i < n) p[i] = 0;
}

// ---------------- CSR build ----------------
__global__ void k_deg(const int* __restrict__ ei, int E, int ET, int* __restrict__ deg) {
    int e = blockIdx.x * blockDim.x + threadIdx.x;
    if (e >= ET) return;
    int d = (e < E) ? ei[E + e] : (e - E);
    atomicAdd(&deg[d], 1);
}

__global__ void k_scan(const int* __restrict__ deg, int* __restrict__ rowptr,
                       int* __restrict__ cursor, int n) {
    __shared__ int sh[1024];
    int t = threadIdx.x;
    int items = (n + 1023) / 1024;
    int b0 = t * items;
    int loc = 0;
    for (int i = 0; i < items; i++) {
        int idx = b0 + i;
        if (idx < n) loc += deg[idx];
    }
    sh[t] = loc;
    __syncthreads();
    for (int off = 1; off < 1024; off <<= 1) {
        int v = (t >= off) ? sh[t - off] : 0;
        __syncthreads();
        sh[t] += v;
        __syncthreads();
    }
    int run = sh[t] - loc;
    for (int i = 0; i < items; i++) {
        int idx = b0 + i;
        if (idx < n) {
            rowptr[idx] = run;
            cursor[idx] = run;
            run += deg[idx];
        }
    }
    if (t == 1023) rowptr[n] = sh[1023];
}

__global__ void k_fill(const int* __restrict__ ei, int E, int ET,
                       int* __restrict__ cursor, int* __restrict__ csrc) {
    int e = blockIdx.x * blockDim.x + threadIdx.x;
    if (e >= ET) return;
    int s, d;
    if (e < E) { s = ei[e]; d = ei[E + e]; }
    else { s = e - E; d = e - E; }
    int pos = atomicAdd(&cursor[d], 1);
    csrc[pos] = s;
}

// graph ranges (batch sorted); also zero feat + bn stat accumulators
__global__ void k_ranges(const int* __restrict__ batch, int n, int* __restrict__ start,
                         float* __restrict__ feat, float* __restrict__ stat) {
    int g = threadIdx.x;
    for (int i = g; i < G_GRAPHS * OUT_DIM; i += 128) feat[i] = 0.f;
    for (int i = g; i < 3 * 2 * HD_MAX; i += 128) stat[i] = 0.f;
    if (g > G_GRAPHS) return;
    if (g == G_GRAPHS) { start[G_GRAPHS] = n; return; }
    int lo = 0, hi = n;
    while (lo < hi) {
        int mid = (lo + hi) >> 1;
        if (batch[mid] < g) lo = mid + 1; else hi = mid;
    }
    start[g] = lo;
}

// ---------------- bf16 split helpers ----------------
__device__ __forceinline__ uint32_t pack_hi(float x0, float x1) {
    __nv_bfloat16 h0 = __float2bfloat16_rn(x0);
    __nv_bfloat16 h1 = __float2bfloat16_rn(x1);
    return (uint32_t)__bfloat16_as_ushort(h0) | ((uint32_t)__bfloat16_as_ushort(h1) << 16);
}
__device__ __forceinline__ uint32_t pack_lo(float x0, float x1) {
    __nv_bfloat16 h0 = __float2bfloat16_rn(x0);
    __nv_bfloat16 h1 = __float2bfloat16_rn(x1);
    __nv_bfloat16 l0 = __float2bfloat16_rn(x0 - __bfloat162float(h0));
    __nv_bfloat16 l1 = __float2bfloat16_rn(x1 - __bfloat162float(h1));
    return (uint32_t)__bfloat16_as_ushort(l0) | ((uint32_t)__bfloat16_as_ushort(l1) << 16);
}
__device__ __forceinline__ void mma_bf16(float* c, const uint32_t* a, uint32_t b0, uint32_t b1) {
    asm volatile(
        "mma.sync.aligned.m16n8k16.row.col.f32.bf16.bf16.f32 "
        "{%0,%1,%2,%3}, {%4,%5,%6,%7}, {%8,%9}, {%0,%1,%2,%3};"
        : "+f"(c[0]), "+f"(c[1]), "+f"(c[2]), "+f"(c[3])
        : "r"(a[0]), "r"(a[1]), "r"(a[2]), "r"(a[3]), "r"(b0), "r"(b1));
}

// ---------------- Tensor-core GEMM: 128x64 tiles, bf16 output --------------------
// bf16 2-term split inputs; C stored as bf16 (gather source); fused BN(prev)+ReLU on
// A load; fused attention-score partials per column block.
#define APAD 136
#define BPAD 72
template <bool FUSE>
__global__ __launch_bounds__(256, 3) void k_gemm_tc(const float* __restrict__ A,
                                                    const float* __restrict__ B,
                                                    __nv_bfloat16* __restrict__ C,
                                                    int M, int K, int Nd, int nNodes,
                                                    const float* __restrict__ bnsum,
                                                    const float* __restrict__ bnsq,
                                                    const float* __restrict__ gamma,
                                                    const float* __restrict__ beta,
                                                    const float* __restrict__ asrc,
                                                    const float* __restrict__ adst,
                                                    float* __restrict__ es,
                                                    float* __restrict__ ed) {
    __shared__ __align__(16) uint32_t Ah[2][8][APAD];
    __shared__ __align__(16) uint32_t Al[2][8][APAD];
    __shared__ __align__(16) uint32_t Bh[2][8][BPAD];
    __shared__ __align__(16) uint32_t Bl[2][8][BPAD];
    __shared__ float ssc[HD_MAX], ssh[HD_MAX];
    __shared__ float sAs[64], sAd[64];
    __shared__ float sE[128][2][2];
    int t = threadIdx.x;
    int bm = blockIdx.x * 128, bn = blockIdx.y * 64;

    if (t < 64) { sAs[t] = asrc[bn + t]; sAd[t] = adst[bn + t]; }
    if (FUSE && t < K) {
        float mu = bnsum[t] / (float)nNodes;
        float var = bnsq[t] / (float)nNodes - mu * mu;
        float sc = gamma[t] * rsqrtf(var + EPS_BN);
        ssc[t] = sc;
        ssh[t] = beta[t] - mu * sc;
    }
    __syncthreads();

    int warp = t >> 5, lane = t & 31;
    int wm = (warp >> 1) * 32, wcol = warp & 1, wn = wcol * 32;
    int gid = lane >> 2, tig = lane & 3;

    int ar = t >> 1, akb = (t & 1) * 8;
    bool avalid = (bm + ar) < M;
    const float* Ap = A + (size_t)(bm + ar) * K + akb;
    const float* Bp = B + (size_t)(warp * 2) * Nd + bn + lane * 2;

    float acc[2][4][4];
#pragma unroll
    for (int mt = 0; mt < 2; mt++)
#pragma unroll
        for (int nt = 0; nt < 4; nt++)
#pragma unroll
            for (int c = 0; c < 4; c++) acc[mt][nt][c] = 0.f;

    float4 a0, a1;
    float2 b0, b1;

    auto stage = [&](int buf, int k0) {
        float v[8] = {a0.x, a0.y, a0.z, a0.w, a1.x, a1.y, a1.z, a1.w};
        if (FUSE) {
#pragma unroll
            for (int j = 0; j < 8; j++)
                v[j] = fmaxf(v[j] * ssc[k0 + akb + j] + ssh[k0 + akb + j], 0.f);
        }
#pragma unroll
        for (int j2 = 0; j2 < 4; j2++) {
            Ah[buf][(akb >> 1) + j2][ar] = pack_hi(v[2 * j2], v[2 * j2 + 1]);
            Al[buf][(akb >> 1) + j2][ar] = pack_lo(v[2 * j2], v[2 * j2 + 1]);
        }
        Bh[buf][warp][lane * 2]     = pack_hi(b0.x, b1.x);
        Bh[buf][warp][lane * 2 + 1] = pack_hi(b0.y, b1.y);
        Bl[buf][warp][lane * 2]     = pack_lo(b0.x, b1.x);
        Bl[buf][warp][lane * 2 + 1] = pack_lo(b0.y, b1.y);
    };

    if (avalid) { a0 = *(const float4*)Ap; a1 = *(const float4*)(Ap + 4); }
    else { a0 = make_float4(0, 0, 0, 0); a1 = a0; }
    b0 = *(const float2*)Bp;
    b1 = *(const float2*)(Bp + Nd);
    stage(0, 0);
    __syncthreads();

    int nk = K >> 4;
    for (int kt = 0; kt < nk; kt++) {
        int buf = kt & 1;
        if (kt + 1 < nk) {
            int k0 = (kt + 1) << 4;
            if (avalid) { a0 = *(const float4*)(Ap + k0); a1 = *(const float4*)(Ap + k0 + 4); }
            else { a0 = make_float4(0, 0, 0, 0); a1 = a0; }
            b0 = *(const float2*)(Bp + (size_t)k0 * Nd);
            b1 = *(const float2*)(Bp + (size_t)(k0 + 1) * Nd);
        }

        uint32_t fbh[4][2], fbl[4][2];
#pragma unroll
        for (int nt = 0; nt < 4; nt++) {
            int c0 = wn + nt * 8 + gid;
            fbh[nt][0] = Bh[buf][tig][c0];
            fbh[nt][1] = Bh[buf][tig + 4][c0];
            fbl[nt][0] = Bl[buf][tig][c0];
            fbl[nt][1] = Bl[buf][tig + 4][c0];
        }
#pragma unroll
        for (int mt = 0; mt < 2; mt++) {
            int r0i = wm + mt * 16 + gid;
            uint32_t ah[4], al[4];
            ah[0] = Ah[buf][tig][r0i];
            ah[1] = Ah[buf][tig][r0i + 8];
            ah[2] = Ah[buf][tig + 4][r0i];
            ah[3] = Ah[buf][tig + 4][r0i + 8];
            al[0] = Al[buf][tig][r0i];
            al[1] = Al[buf][tig][r0i + 8];
            al[2] = Al[buf][tig + 4][r0i];
            al[3] = Al[buf][tig + 4][r0i + 8];
#pragma unroll
            for (int nt = 0; nt < 4; nt++)
                mma_bf16(acc[mt][nt], ah, fbh[nt][0], fbh[nt][1]);
#pragma unroll
            for (int nt = 0; nt < 4; nt++)
                mma_bf16(acc[mt][nt], ah, fbl[nt][0], fbl[nt][1]);
#pragma unroll
            for (int nt = 0; nt < 4; nt++)
                mma_bf16(acc[mt][nt], al, fbh[nt][0], fbh[nt][1]);
        }

        if (kt + 1 < nk) {
            int k0 = (kt + 1) << 4;
            stage(buf ^ 1, k0);
        }
        __syncthreads();
    }

    // ---- epilogue: store C (bf16) + attention-score partials ----
    uint32_t* Cb = (uint32_t*)C;
#pragma unroll
    for (int mt = 0; mt < 2; mt++) {
        int r0i = bm + wm + mt * 16 + gid;
        int r1i = r0i + 8;
#pragma unroll
        for (int nt = 0; nt < 4; nt++) {
            int cc = bn + wn + nt * 8 + tig * 2;
            if (r0i < M) Cb[((size_t)r0i * Nd + cc) >> 1] =
                pack_hi(acc[mt][nt][0], acc[mt][nt][1]);
            if (r1i < M) Cb[((size_t)r1i * Nd + cc) >> 1] =
                pack_hi(acc[mt][nt][2], acc[mt][nt][3]);
        }
#pragma unroll
        for (int half = 0; half < 2; half++) {
            float pes = 0.f, ped = 0.f;
#pragma unroll
            for (int nt = 0; nt < 4; nt++) {
#pragma unroll
                for (int j = 0; j < 2; j++) {
                    int cl = wn + nt * 8 + tig * 2 + j;
                    float v = acc[mt][nt][half * 2 + j];
                    pes += v * sAs[cl];
                    ped += v * sAd[cl];
                }
            }
            pes += __shfl_xor_sync(0xffffffffu, pes, 1);
            pes += __shfl_xor_sync(0xffffffffu, pes, 2);
            ped += __shfl_xor_sync(0xffffffffu, ped, 1);
            ped += __shfl_xor_sync(0xffffffffu, ped, 2);
            if (tig == 0) {
                int r = wm + mt * 16 + gid + half * 8;
                sE[r][wcol][0] = pes;
                sE[r][wcol][1] = ped;
            }
        }
    }
    __syncthreads();
    if (t < 128) {
        int row = bm + t;
        if (row < M) {
            es[row * 4 + blockIdx.y] = sE[t][0][0] + sE[t][1][0];
            ed[row * 4 + blockIdx.y] = sE[t][0][1] + sE[t][1][1];
        }
    }
}

// ---------------- single-pass softmax + aggregation (bf16 gather) + BN stats --------
template <int H, int D>
__global__ __launch_bounds__(256) void k_agg_fused(
        const __nv_bfloat16* __restrict__ h, const float* __restrict__ es,
        const float* __restrict__ ed, const int* __restrict__ rowptr,
        const int* __restrict__ csrc, const float* __restrict__ bias,
        float* __restrict__ outp, float* __restrict__ bnsum,
        float* __restrict__ bnsq, int n) {
    constexpr int HD = H * D, PL = HD / 32, NV = PL / 4;  // PL=8 or 4 channels/lane
    __shared__ float sm8[8][HD];
    int t = threadIdx.x;
    int node = (blockIdx.x * 256 + t) >> 5;
    int lane = t & 31;
    int warp = t >> 5;
    const int hme = (lane * PL) / D;

    float4 res[NV];
#pragma unroll
    for (int q = 0; q < NV; q++) res[q] = make_float4(0.f, 0.f, 0.f, 0.f);

    if (node < n) {
        float edme;
        if (H == 1) edme = ed[node * 4] + ed[node * 4 + 1];
        else        edme = ed[node * 4 + hme];
        int p0 = rowptr[node], p1 = rowptr[node + 1];
        float4 acc[NV];
#pragma unroll
        for (int q = 0; q < NV; q++) acc[q] = make_float4(0.f, 0.f, 0.f, 0.f);
        float z = 0.f;
#pragma unroll 2
        for (int p = p0; p < p1; p++) {
            int s = csrc[p];
            float e;
            if (H == 1) {
                float2 e2 = *(const float2*)&es[s * 4];
                e = e2.x + e2.y + edme;
            } else {
                e = es[s * 4 + hme] + edme;
            }
            e = (e > 0.f) ? e : NEG_SLOPE * e;
            float w = __expf(e);
            z += w;
            const __nv_bfloat16* hs = h + (size_t)s * HD + lane * PL;
            uint32_t u[PL / 2];
            if (PL == 8) *(uint4*)u = *(const uint4*)hs;
            else         *(uint2*)u = *(const uint2*)hs;
#pragma unroll
            for (int q = 0; q < NV; q++) {
                float2 f0 = __bfloat1622float2(*(__nv_bfloat162*)&u[q * 2]);
                float2 f1 = __bfloat1622float2(*(__nv_bfloat162*)&u[q * 2 + 1]);
                acc[q].x += f0.x * w; acc[q].y += f0.y * w;
                acc[q].z += f1.x * w; acc[q].w += f1.y * w;
            }
        }
        float iz = 1.f / z;
        const float4* bb = (const float4*)(bias + lane * PL);
        float4* op = (float4*)(outp + (size_t)node * HD + lane * PL);
#pragma unroll
        for (int q = 0; q < NV; q++) {
            float4 b = bb[q];
            res[q] = make_float4(acc[q].x * iz + b.x, acc[q].y * iz + b.y,
                                 acc[q].z * iz + b.z, acc[q].w * iz + b.w);
            op[q] = res[q];
        }
    }

    // BN stats: stage rows in smem, channel-wise reduce, 2 global atomics/ch/block
#pragma unroll
    for (int q = 0; q < NV; q++)
        *(float4*)&sm8[warp][lane * PL + q * 4] = res[q];
    __syncthreads();
    if (t < HD) {
        float s = 0.f, q2 = 0.f;
#pragma unroll
        for (int w = 0; w < 8; w++) {
            float v = sm8[w][t];
            s += v;
            q2 += v * v;
        }
        atomicAdd(&bnsum[t], s);
        atomicAdd(&bnsq[t], q2);
    }
}

// ---------------- pooling (BN scale/shift computed in-block from stats) -------------
__global__ void k_pool(const float* __restrict__ o, const int* __restrict__ start,
                       const float* __restrict__ bnsum, const float* __restrict__ bnsq,
                       const float* __restrict__ gamma, const float* __restrict__ beta,
                       int n, float* __restrict__ feat) {
    __shared__ float sm[4][OUT_DIM];
    __shared__ float ssc[OUT_DIM], ssh[OUT_DIM];
    int c = threadIdx.x & 127;
    int rgrp = threadIdx.x >> 7;
    if (threadIdx.x < OUT_DIM) {
        float mu = bnsum[c] / (float)n;
        float var = bnsq[c] / (float)n - mu * mu;
        float sc2 = gamma[c] * rsqrtf(var + EPS_BN);
        ssc[c] = sc2;
        ssh[c] = beta[c] - mu * sc2;
    }
    __syncthreads();
    int g = blockIdx.x;
    int part = blockIdx.y;
    int s0 = start[g], s1 = start[g + 1];
    int len = s1 - s0;
    int chunk = (len + 3) >> 2;
    int r0 = s0 + part * chunk;
    int r1 = min(s1, r0 + chunk);
    float sc = ssc[c], sh = ssh[c];
    float sum = 0.f;
    for (int r = r0 + rgrp; r < r1; r += 4) {
        float v = o[(size_t)r * OUT_DIM + c];
        sum += fmaxf(v * sc + sh, 0.f);
    }
    sm[rgrp][c] = sum;
    __syncthreads();
    if (threadIdx.x < OUT_DIM) {
        float s = sm[0][c] + sm[1][c] + sm[2][c] + sm[3][c];
        atomicAdd(&feat[g * OUT_DIM + c], s);
    }
}

// ---------------- heads ----------------
__global__ void k_heads(const float* __restrict__ featsum, const int* __restrict__ start,
                        const float* __restrict__ clfW, const float* __restrict__ clfb,
                        const float* __restrict__ dW1, const float* __restrict__ db1,
                        const float* __restrict__ dW2, const float* __restrict__ db2,
                        float* __restrict__ out) {
    __shared__ float f[OUT_DIM];
    __shared__ float dh[64];
    int g = blockIdx.x, t = threadIdx.x;
    float c = (float)max(start[g + 1] - start[g], 1);
    f[t] = featsum[g * OUT_DIM + t] / c;
    out[G_GRAPHS * NCLS_D + G_GRAPHS * 2 + g * OUT_DIM + t] = f[t];
    __syncthreads();
    if (t < 64) {
        float s = db1[t];
        for (int k = 0; k < OUT_DIM; k++) s += f[k] * dW1[k * 64 + t];
        dh[t] = fmaxf(s, 0.f);
    }
    if (t < NCLS_D) {
        float s = clfb[t];
        for (int k = 0; k < OUT_DIM; k++) s += f[k] * clfW[k * NCLS_D + t];
        out[g * NCLS_D + t] = s;
    }
    __syncthreads();
    if (t < 2) {
        float s = db2[t];
        for (int k = 0; k < 64; k++) s += dh[k] * dW2[k * 2 + t];
        out[G_GRAPHS * NCLS_D + g * 2 + t] = s;
    }
}

// ---------------- launch ----------------
static inline int cdiv(int a, int b) { return (a + b - 1) / b; }

extern "C" void kernel_launch(void* const* d_in, const int* in_sizes, int n_in,
                              void* d_out, int out_size) {
    const float* x = (const float*)d_in[0];
    const int* ei = (const int*)d_in[1];
    const int* batch = (const int*)d_in[2];
    const float* W[3]   = {(const float*)d_in[3],  (const float*)d_in[9],  (const float*)d_in[15]};
    const float* Asr[3] = {(const float*)d_in[4],  (const float*)d_in[10], (const float*)d_in[16]};
    const float* Ads[3] = {(const float*)d_in[5],  (const float*)d_in[11], (const float*)d_in[17]};
    const float* Bi[3]  = {(const float*)d_in[6],  (const float*)d_in[12], (const float*)d_in[18]};
    const float* Ga[3]  = {(const float*)d_in[7],  (const float*)d_in[13], (const float*)d_in[19]};
    const float* Be[3]  = {(const float*)d_in[8],  (const float*)d_in[14], (const float*)d_in[20]};
    const float* clfW = (const float*)d_in[21];
    const float* clfb = (const float*)d_in[22];
    const float* dW1 = (const float*)d_in[23];
    const float* db1 = (const float*)d_in[24];
    const float* dW2 = (const float*)d_in[25];
    const float* db2 = (const float*)d_in[26];

    int N = in_sizes[0] / F_IN_D;
    int E = in_sizes[1] / 2;
    int ET = E + N;

    float *p_o, *p_es, *p_ed, *p_stat, *p_feat;
    __nv_bfloat16* p_h;
    int *p_deg, *p_rowptr, *p_cursor, *p_csrc, *p_start;
    cudaGetSymbolAddress((void**)&p_h, g_h);
    cudaGetSymbolAddress((void**)&p_o, g_o);
    cudaGetSymbolAddress((void**)&p_es, g_es);
    cudaGetSymbolAddress((void**)&p_ed, g_ed);
    cudaGetSymbolAddress((void**)&p_deg, g_deg);
    cudaGetSymbolAddress((void**)&p_rowptr, g_rowptr);
    cudaGetSymbolAddress((void**)&p_cursor, g_cursor);
    cudaGetSymbolAddress((void**)&p_csrc, g_csrc);
    cudaGetSymbolAddress((void**)&p_stat, g_bnstat);
    cudaGetSymbolAddress((void**)&p_feat, g_feat);
    cudaGetSymbolAddress((void**)&p_start, g_start);

    const int Kd[3] = {F_IN_D, 256, 256};
    const int Hh[3] = {4, 4, 1};

    // GEMM layer0 at launch index 3 so the ncu window lands on it.
    k_zero_i<<<cdiv(N, 256), 256>>>(p_deg, N);
    k_deg<<<cdiv(ET, 256), 256>>>(ei, E, ET, p_deg);
    k_scan<<<1, 1024>>>(p_deg, p_rowptr, p_cursor, N);
    {
        dim3 gg(cdiv(N, 128), 4);
        k_gemm_tc<false><<<gg, 256>>>(x, W[0], p_h, N, Kd[0], 256, N,
                                      nullptr, nullptr, nullptr, nullptr,
                                      Asr[0], Ads[0], p_es, p_ed);
    }
    k_fill<<<cdiv(ET, 256), 256>>>(ei, E, ET, p_cursor, p_csrc);
    k_ranges<<<1, 128>>>(batch, N, p_start, p_feat, p_stat);

    for (int li = 0; li < 3; li++) {
        int HD = (li < 2) ? 256 : 128;
        float* bnsum = p_stat + li * 2 * HD_MAX;
        float* bnsq = bnsum + HD_MAX;
        if (li > 0) {
            float* psum = p_stat + (li - 1) * 2 * HD_MAX;
            float* psq = psum + HD_MAX;
            dim3 gg(cdiv(N, 128), HD / 64);
            k_gemm_tc<true><<<gg, 256>>>(p_o, W[li], p_h, N, Kd[li], HD, N,
                                         psum, psq, Ga[li - 1], Be[li - 1],
                                         Asr[li], Ads[li], p_es, p_ed);
        }

        int aggBlocks = cdiv(N * 32, 256);
        if (Hh[li] == 4) {
            k_agg_fused<4, 64><<<aggBlocks, 256>>>(p_h, p_es, p_ed, p_rowptr, p_csrc,
                                                   Bi[li], p_o, bnsum, bnsq, N);
        } else {
            k_agg_fused<1, 128><<<aggBlocks, 256>>>(p_h, p_es, p_ed, p_rowptr, p_csrc,
                                                    Bi[li], p_o, bnsum, bnsq, N);
        }
    }

    // --- pooling + heads (layer-2 BN folded into pool) ---
    {
        float* bnsum2 = p_stat + 2 * 2 * HD_MAX;
        float* bnsq2 = bnsum2 + HD_MAX;
        dim3 pg(G_GRAPHS, 4);
        k_pool<<<pg, 512>>>(p_o, p_start, bnsum2, bnsq2, Ga[2], Be[2], N, p_feat);
    }
    k_heads<<<G_GRAPHS, 128>>>(p_feat, p_start, clfW, clfb, dW1, db1, dW2, db2,
                               (float*)d_out);
}